// round 10
// baseline (speedup 1.0000x reference)
#include <cuda_runtime.h>
#include <cuda_bf16.h>
#include <cstdint>

#define BB 256     // batch
#define TT 256     // time steps
#define DD 64      // input dim
#define HH 512     // hidden
#define OO 10      // output classes

#define NBLK 128   // rec grid: 16 bt x 8 jt; cluster = 8 jt CTAs of one bt

// ---------------- scratch (static device globals; no allocation allowed) ----
__device__ float    g_xp0[TT * BB * HH];     // [t][b][h] fp32
__device__ float    g_xp1[TT * BB * HH];     // [t][b][h] fp32
__device__ uint32_t g_seqp[TT * BB * HH];    // layer-0 h_t packed hi|lo bf16
__device__ uint32_t g_hpk[2][BB * HH];       // layer-1 h ping-pong packed
__device__ float    g_hlast[BB * HH];

// bf16 split weights for the HMMA input projections
__device__ __nv_bfloat16 g_w0h[HH * DD], g_w0l[HH * DD];
__device__ __nv_bfloat16 g_w1h[HH * HH], g_w1l[HH * HH];

// ---------------- HMMA plumbing ---------------------------------------------
__device__ __forceinline__ uint32_t s2u(const void* p) {
    uint32_t a;
    asm("{ .reg .u64 t; cvta.to.shared.u64 t, %1; cvt.u32.u64 %0, t; }"
        : "=r"(a) : "l"(p));
    return a;
}
__device__ __forceinline__ void ldm_x4(uint32_t& r0, uint32_t& r1,
                                       uint32_t& r2, uint32_t& r3,
                                       uint32_t addr) {
    asm volatile("ldmatrix.sync.aligned.m8n8.x4.shared.b16 {%0,%1,%2,%3}, [%4];"
                 : "=r"(r0), "=r"(r1), "=r"(r2), "=r"(r3) : "r"(addr));
}
__device__ __forceinline__ void ldm_x2(uint32_t& r0, uint32_t& r1,
                                       uint32_t addr) {
    asm volatile("ldmatrix.sync.aligned.m8n8.x2.shared.b16 {%0,%1}, [%2];"
                 : "=r"(r0), "=r"(r1) : "r"(addr));
}
__device__ __forceinline__ void mma_bf16(float* d, const uint32_t* a,
                                         uint32_t b0, uint32_t b1) {
    asm volatile(
        "mma.sync.aligned.m16n8k16.row.col.f32.bf16.bf16.f32 "
        "{%0,%1,%2,%3}, {%4,%5,%6,%7}, {%8,%9}, {%0,%1,%2,%3};"
        : "+f"(d[0]), "+f"(d[1]), "+f"(d[2]), "+f"(d[3])
        : "r"(a[0]), "r"(a[1]), "r"(a[2]), "r"(a[3]), "r"(b0), "r"(b1));
}
__device__ __forceinline__ uint32_t packsplit(float v) {
    __nv_bfloat16 h = __float2bfloat16(v);
    __nv_bfloat16 l = __float2bfloat16(v - __bfloat162float(h));
    return (uint32_t)__bfloat16_as_ushort(h) |
           ((uint32_t)__bfloat16_as_ushort(l) << 16);
}
__device__ __forceinline__ void cluster_sync_() {
    asm volatile("barrier.cluster.arrive.aligned;" ::: "memory");
    asm volatile("barrier.cluster.wait.aligned;" ::: "memory");
}

// ---------------- weight convert: fp32 -> bf16 hi/lo ------------------------
__global__ void convert_w(const float* __restrict__ w0,
                          const float* __restrict__ w1) {
    int i = blockIdx.x * 256 + threadIdx.x;
    if (i < HH * DD) {
        float v = w0[i];
        __nv_bfloat16 h = __float2bfloat16(v);
        g_w0h[i] = h;
        g_w0l[i] = __float2bfloat16(v - __bfloat162float(h));
    }
    if (i < HH * HH) {
        float v = w1[i];
        __nv_bfloat16 h = __float2bfloat16(v);
        g_w1h[i] = h;
        g_w1l[i] = __float2bfloat16(v - __bfloat162float(h));
    }
}

// ---------------- HMMA GEMM: C = A @ W^T + b1 + b2 --------------------------
// Split bf16: C = Ah*Wh + Ah*Wl + Al*Wh, fp32 accum.
// Tile 128m x 128n, BK=32, 256 threads (8 warps = 4m x 2n), warp 32m x 64n.
// packed=1: A rows are uint32 (hi|lo<<16) pre-split bf16 pairs.
#define HM_AH 0
#define HM_AL 8192
#define HM_WH 16384
#define HM_WL 24576
#define HM_SB 32768          // staged bias: 128 floats
#define HM_TOTAL (32768 + 512)

__global__ __launch_bounds__(256, 2) void gemm_hmma(
    const float* __restrict__ A,
    const __nv_bfloat16* __restrict__ Wh, const __nv_bfloat16* __restrict__ Wl,
    const float* __restrict__ b1, const float* __restrict__ b2,
    float* __restrict__ Cm, int K, int permute, int packed)
{
    __shared__ __align__(128) uint8_t sm[HM_TOTAL];
    uint32_t sbase = s2u(sm);

    int tid = threadIdx.x;
    int lane = tid & 31;
    int wid = tid >> 5;
    int wm = wid & 3;
    int wn = wid >> 2;
    int m0 = blockIdx.x * 128;
    int n0 = blockIdx.y * 128;

    if (tid < 128) {
        int n = n0 + tid;
        ((float*)(sm + HM_SB))[tid] = b1[n] + (b2 ? b2[n] : 0.f);
    }

    const float* Ap[4];
#pragma unroll
    for (int it = 0; it < 4; ++it) {
        int idx = tid + it * 256;
        int row = idx >> 3;
        int gm = m0 + row;
        if (permute) {
            int b_ = gm & (BB - 1);
            int t_ = gm >> 8;                  // BB == 256
            Ap[it] = A + ((size_t)b_ * TT + t_) * K;
        } else {
            Ap[it] = A + (size_t)gm * K;
        }
    }

    float acc[2][8][4];
#pragma unroll
    for (int mf = 0; mf < 2; ++mf)
#pragma unroll
        for (int nf = 0; nf < 8; ++nf)
#pragma unroll
            for (int q = 0; q < 4; ++q) acc[mf][nf][q] = 0.f;

    int sub = lane >> 3;
    int r8  = lane & 7;

    int nch = K >> 5;
    for (int c = 0; c < nch; ++c) {
        int kc = c << 5;
        __syncthreads();

#pragma unroll
        for (int it = 0; it < 4; ++it) {
            int idx = tid + it * 256;
            int row = idx >> 3, kq = idx & 7;
            uint2 hp, lp;
            if (packed) {
                uint4 p = *(const uint4*)((const uint32_t*)Ap[it] + kc + kq * 4);
                hp.x = (p.x & 0xffffu) | (p.y << 16);
                hp.y = (p.z & 0xffffu) | (p.w << 16);
                lp.x = (p.x >> 16) | (p.y & 0xffff0000u);
                lp.y = (p.z >> 16) | (p.w & 0xffff0000u);
            } else {
                float4 v = *(const float4*)(Ap[it] + kc + kq * 4);
                uint32_t s0 = packsplit(v.x), s1 = packsplit(v.y);
                uint32_t s2 = packsplit(v.z), s3 = packsplit(v.w);
                hp.x = (s0 & 0xffffu) | (s1 << 16);
                hp.y = (s2 & 0xffffu) | (s3 << 16);
                lp.x = (s0 >> 16) | (s1 & 0xffff0000u);
                lp.y = (s2 >> 16) | (s3 & 0xffff0000u);
            }
            int kt = kq >> 1, kcol = (kq & 1) * 4;
            uint32_t off = (uint32_t)(((kt * 16) + (row >> 3)) * 128 +
                                      (row & 7) * 16 + kcol * 2);
            *(uint2*)(sm + HM_AH + off) = hp;
            *(uint2*)(sm + HM_AL + off) = lp;
        }
#pragma unroll
        for (int it = 0; it < 4; ++it) {
            int idx = tid + it * 256;
            int row = idx >> 3, kq = idx & 7;
            size_t go = (size_t)(n0 + row) * K + kc + kq * 4;
            uint2 hv = *(const uint2*)(Wh + go);
            uint2 lv = *(const uint2*)(Wl + go);
            int kt = kq >> 1, kcol = (kq & 1) * 4;
            uint32_t off = (uint32_t)(((kt * 16) + (row >> 3)) * 128 +
                                      (row & 7) * 16 + kcol * 2);
            *(uint2*)(sm + HM_WH + off) = hv;
            *(uint2*)(sm + HM_WL + off) = lv;
        }
        __syncthreads();

#pragma unroll
        for (int s = 0; s < 2; ++s) {
            uint32_t ah[2][4], al[2][4];
#pragma unroll
            for (int mf = 0; mf < 2; ++mf) {
                int mt = wm * 4 + mf * 2 + (sub & 1);
                int kt = s * 2 + (sub >> 1);
                uint32_t ad = sbase + HM_AH +
                              (uint32_t)(((kt * 16) + mt) * 128 + r8 * 16);
                ldm_x4(ah[mf][0], ah[mf][1], ah[mf][2], ah[mf][3], ad);
                ldm_x4(al[mf][0], al[mf][1], al[mf][2], al[mf][3],
                       ad + (HM_AL - HM_AH));
            }
#pragma unroll
            for (int nf = 0; nf < 8; ++nf) {
                int nt = wn * 8 + nf;
                int ktb = s * 2 + (sub & 1);
                uint32_t bd = sbase + HM_WH +
                              (uint32_t)(((ktb * 16) + nt) * 128 + r8 * 16);
                uint32_t bh0, bh1, bl0, bl1;
                ldm_x2(bh0, bh1, bd);
                ldm_x2(bl0, bl1, bd + (HM_WL - HM_WH));
                mma_bf16(acc[0][nf], ah[0], bh0, bh1);
                mma_bf16(acc[1][nf], ah[1], bh0, bh1);
                mma_bf16(acc[0][nf], ah[0], bl0, bl1);
                mma_bf16(acc[1][nf], ah[1], bl0, bl1);
                mma_bf16(acc[0][nf], al[0], bh0, bh1);
                mma_bf16(acc[1][nf], al[1], bh0, bh1);
            }
        }
    }

    const float* sb = (const float*)(sm + HM_SB);
#pragma unroll
    for (int mf = 0; mf < 2; ++mf) {
        int mrow = m0 + wm * 32 + mf * 16 + (lane >> 2);
#pragma unroll
        for (int nf = 0; nf < 8; ++nf) {
            int ncol = wn * 64 + nf * 8 + (lane & 3) * 2;
            float bb0 = sb[ncol], bb1 = sb[ncol + 1];
            float2 v0, v1;
            v0.x = acc[mf][nf][0] + bb0; v0.y = acc[mf][nf][1] + bb1;
            v1.x = acc[mf][nf][2] + bb0; v1.y = acc[mf][nf][3] + bb1;
            *(float2*)(Cm + (size_t)mrow * HH + n0 + ncol) = v0;
            *(float2*)(Cm + (size_t)(mrow + 8) * HH + n0 + ncol) = v1;
        }
    }
}

// ---------------- persistent HMMA recurrence kernel (cluster-synced) --------
// h_t = relu(xp[t] + h_{t-1} @ Whh^T), h_0 = relu(xp[0]).
// Grid 128 = 16 bt x 8 jt. CTA tile: 16b x 64j, FULL K=512.
// Cluster (8 CTAs) == the exact dependency scope: the 8 jt CTAs of one bt.
// barrier.cluster.arrive(release)/wait(acquire) replaces the L2 atomic
// barrier; bt chains are fully independent (no cross-cluster dependency).
// Whh hi/lo persists in SMEM; h exchanged packed hi|lo bf16 via L2.
// 8 warps: warp wid owns n8 j-block wid (m16 shared).
#define RS_WH 0
#define RS_WL 65536
#define RS_AH 131072
#define RS_AL 147456
#define RS_TOTAL 163840

__global__ __launch_bounds__(256, 1) __cluster_dims__(8, 1, 1)
void rec_kernel(
    const float* __restrict__ xp,      // [T][B][H]
    const float* __restrict__ Whh,     // [H][H] fp32
    uint32_t* __restrict__ hist,       // packed h ring: [(mask+1)][B][H]
    int hmask,                         // TT-1 (full seq) or 1 (ping-pong)
    float* __restrict__ h_last)        // [B][H] fp32 or nullptr
{
    extern __shared__ uint8_t sm[];
    uint32_t sb = s2u(sm);

    int cid = blockIdx.x;
    int bt = cid >> 3;                 // 0..15
    int jt = cid & 7;                  // 0..7 == cluster rank
    int b0 = bt * 16, j0 = jt * 64;

    int tid = threadIdx.x;
    int lane = tid & 31, wid = tid >> 5;
    int sub = lane >> 3, r8 = lane & 7;
    int jb = wid;                      // n8 j-block 0..7

    // ---- preload Whh slice (64 j-rows x 512 k) hi/lo, swizzled blocks -----
    // blocks: kb (k8 index 0..63) x rowblock (0..7); 128 B per (kb,rb)
    for (int idx = tid; idx < 8192; idx += 256) {
        int row = idx >> 7, kq = idx & 127;          // kq: 4-elem k group
        float4 v = *(const float4*)(Whh + (size_t)(j0 + row) * HH + kq * 4);
        uint32_t s0 = packsplit(v.x), s1 = packsplit(v.y);
        uint32_t s2 = packsplit(v.z), s3 = packsplit(v.w);
        uint2 hi, lo;
        hi.x = (s0 & 0xffffu) | (s1 << 16);
        hi.y = (s2 & 0xffffu) | (s3 << 16);
        lo.x = (s0 >> 16) | (s1 & 0xffff0000u);
        lo.y = (s2 >> 16) | (s3 & 0xffff0000u);
        int kb = kq >> 1;
        uint32_t off = (uint32_t)kb * 1024u + (uint32_t)(row >> 3) * 128u +
                       ((uint32_t)((row & 7) ^ (kb & 7)) << 4) +
                       (uint32_t)(kq & 1) * 8u;
        *(uint2*)(sm + RS_WH + off) = hi;
        *(uint2*)(sm + RS_WL + off) = lo;
    }

    // output fragment coordinates (m16n8 D layout)
    int brow = b0 + (lane >> 2);
    int jcol = j0 + jb * 8 + (lane & 3) * 2;

    for (int t = 0; t < TT; ++t) {
        float acc[4] = {0.f, 0.f, 0.f, 0.f};

        if (t > 0) {
            // ---- stage h_{t-1}: 16 rows x 512 k packed -> AH/AL ----------
            const uint32_t* hsrc = hist + (size_t)((t - 1) & hmask) * BB * HH;
#pragma unroll
            for (int it = 0; it < 8; ++it) {
                int idx = tid + it * 256;
                int row = idx >> 7, kq = idx & 127;
                uint4 p = *(const uint4*)(hsrc + (size_t)(b0 + row) * HH + kq * 4);
                uint2 hi, lo;
                hi.x = (p.x & 0xffffu) | (p.y << 16);
                hi.y = (p.z & 0xffffu) | (p.w << 16);
                lo.x = (p.x >> 16) | (p.y & 0xffff0000u);
                lo.y = (p.z >> 16) | (p.w & 0xffff0000u);
                int kb = kq >> 1;
                uint32_t off = (uint32_t)kb * 256u +
                               (uint32_t)(row >> 3) * 128u +
                               ((uint32_t)((row & 7) ^ (kb & 7)) << 4) +
                               (uint32_t)(kq & 1) * 8u;
                *(uint2*)(sm + RS_AH + off) = hi;
                *(uint2*)(sm + RS_AL + off) = lo;
            }
            __syncthreads();

            // ---- 3-pass HMMA over K=512 (32 k16 tiles) -------------------
#pragma unroll 4
            for (int ks = 0; ks < 32; ++ks) {
                int kbA = ks * 2 + (sub >> 1);
                uint32_t aoff = (uint32_t)kbA * 256u +
                                (uint32_t)(sub & 1) * 128u +
                                ((uint32_t)(r8 ^ (kbA & 7)) << 4);
                uint32_t ah[4], al[4];
                ldm_x4(ah[0], ah[1], ah[2], ah[3], sb + RS_AH + aoff);
                ldm_x4(al[0], al[1], al[2], al[3], sb + RS_AL + aoff);

                int kbB = ks * 2 + (sub & 1);
                uint32_t boff = (uint32_t)kbB * 1024u + (uint32_t)jb * 128u +
                                ((uint32_t)(r8 ^ (kbB & 7)) << 4);
                uint32_t bh0, bh1, bl0, bl1;
                ldm_x2(bh0, bh1, sb + RS_WH + boff);
                ldm_x2(bl0, bl1, sb + RS_WL + boff);

                mma_bf16(acc, ah, bh0, bh1);
                mma_bf16(acc, ah, bl0, bl1);
                mma_bf16(acc, al, bh0, bh1);
            }
            __syncthreads();   // A-stage buffers free for next step
        }

        // ---- output: v = relu(acc + xp[t]); publish packed ---------------
        const float* xpt = xp + (size_t)t * BB * HH;
        float2 x0 = *(const float2*)(xpt + (size_t)brow * HH + jcol);
        float2 x1 = *(const float2*)(xpt + (size_t)(brow + 8) * HH + jcol);
        float v0 = fmaxf(acc[0] + x0.x, 0.f);
        float v1 = fmaxf(acc[1] + x0.y, 0.f);
        float v2 = fmaxf(acc[2] + x1.x, 0.f);
        float v3 = fmaxf(acc[3] + x1.y, 0.f);

        uint32_t* hdst = hist + (size_t)(t & hmask) * BB * HH;
        uint2 pa, pb;
        pa.x = packsplit(v0); pa.y = packsplit(v1);
        pb.x = packsplit(v2); pb.y = packsplit(v3);
        *(uint2*)(hdst + (size_t)brow * HH + jcol) = pa;
        *(uint2*)(hdst + (size_t)(brow + 8) * HH + jcol) = pb;

        if (h_last && t == TT - 1) {
            *(float2*)(h_last + (size_t)brow * HH + jcol) =
                make_float2(v0, v1);
            *(float2*)(h_last + (size_t)(brow + 8) * HH + jcol) =
                make_float2(v2, v3);
        }

        // release h_t to the cluster / acquire peers' h_t
        cluster_sync_();
    }
}

// ---------------- head: relu(h @ fc1^T + b1) @ fc2^T + b2 -------------------
__global__ __launch_bounds__(256) void head_kernel(
    const float* __restrict__ hl, const float* __restrict__ w1,
    const float* __restrict__ b1f, const float* __restrict__ w2,
    const float* __restrict__ b2f, float* __restrict__ out)
{
    __shared__ float sh[8];
    int b = blockIdx.x;
    int tid = threadIdx.x;
    int w = tid >> 5;
    int lane = tid & 31;

    const float* hb = hl + (size_t)b * HH;
    const float* wr = w1 + (size_t)w * HH;
    float ssum = 0.f;
    for (int k = lane; k < HH; k += 32) ssum += hb[k] * wr[k];
#pragma unroll
    for (int o = 16; o; o >>= 1) ssum += __shfl_xor_sync(0xffffffffu, ssum, o);
    if (lane == 0) sh[w] = fmaxf(ssum + b1f[w], 0.f);
    __syncthreads();
    if (tid < OO) {
        float r = b2f[tid];
#pragma unroll
        for (int j = 0; j < 8; ++j) r += sh[j] * w2[tid * 8 + j];
        out[(size_t)b * OO + tid] = r;
    }
}

// ---------------- launch ----------------------------------------------------
extern "C" void kernel_launch(void* const* d_in, const int* in_sizes, int n_in,
                              void* d_out, int out_size)
{
    const float* x     = (const float*)d_in[0];
    const float* w_ih0 = (const float*)d_in[1];
    const float* w_hh0 = (const float*)d_in[2];
    const float* b_ih0 = (const float*)d_in[3];
    const float* b_hh0 = (const float*)d_in[4];
    const float* w_ih1 = (const float*)d_in[5];
    const float* w_hh1 = (const float*)d_in[6];
    const float* b_ih1 = (const float*)d_in[7];
    const float* b_hh1 = (const float*)d_in[8];
    const float* fc1_w = (const float*)d_in[9];
    const float* fc1_b = (const float*)d_in[10];
    const float* fc2_w = (const float*)d_in[11];
    const float* fc2_b = (const float*)d_in[12];
    float* out = (float*)d_out;

    void* p;
    cudaGetSymbolAddress(&p, g_xp0);   float* xp0 = (float*)p;
    cudaGetSymbolAddress(&p, g_xp1);   float* xp1 = (float*)p;
    cudaGetSymbolAddress(&p, g_seqp);  uint32_t* seqp = (uint32_t*)p;
    cudaGetSymbolAddress(&p, g_hpk);   uint32_t* hpk = (uint32_t*)p;
    cudaGetSymbolAddress(&p, g_hlast); float* hlast = (float*)p;
    cudaGetSymbolAddress(&p, g_w0h);   __nv_bfloat16* w0h = (__nv_bfloat16*)p;
    cudaGetSymbolAddress(&p, g_w0l);   __nv_bfloat16* w0l = (__nv_bfloat16*)p;
    cudaGetSymbolAddress(&p, g_w1h);   __nv_bfloat16* w1h = (__nv_bfloat16*)p;
    cudaGetSymbolAddress(&p, g_w1l);   __nv_bfloat16* w1l = (__nv_bfloat16*)p;

    cudaFuncSetAttribute(rec_kernel,
                         cudaFuncAttributeMaxDynamicSharedMemorySize,
                         RS_TOTAL);

    dim3 gg(TT * BB / 128, HH / 128);   // 512 x 4

    // split weights for HMMA projections
    convert_w<<<(HH * HH + 255) / 256, 256>>>(w_ih0, w_ih1);
    // layer-0 input projection (HMMA; rows permuted from x[b][t][d])
    gemm_hmma<<<gg, 256>>>(x, w0h, w0l, b_ih0, b_hh0, xp0, DD, 1, 0);
    // layer-0 recurrence: cluster-synced HMMA, writes packed seq
    rec_kernel<<<NBLK, 256, RS_TOTAL>>>(xp0, w_hh0, seqp, TT - 1, nullptr);
    // layer-1 input projection (HMMA, packed-A from seqp)
    gemm_hmma<<<gg, 256>>>((const float*)seqp, w1h, w1l, b_ih1, b_hh1, xp1,
                           HH, 0, 1);
    // layer-1 recurrence: ping-pong packed h, emits fp32 h_last
    rec_kernel<<<NBLK, 256, RS_TOTAL>>>(xp1, w_hh1, hpk, 1, hlast);
    // head
    head_kernel<<<BB, 256>>>(hlast, fc1_w, fc1_b, fc2_w, fc2_b, out);
}

// round 12
// speedup vs baseline: 1.8958x; 1.8958x over previous
#include <cuda_runtime.h>
#include <cuda_bf16.h>
#include <cstdint>

#define BB 256     // batch
#define TT 256     // time steps
#define DD 64      // input dim
#define HH 512     // hidden
#define OO 10      // output classes

#define NBLK 128   // fused rec grid: 8 bt x 16 jt (all co-resident, 1/SM)
#define GRP  16    // CTAs per bt dependency group

// ---------------- scratch (static device globals; no allocation allowed) ----
__device__ float    g_xp0[TT * BB * HH];     // [t][b][h] fp32 (layer-0 inproj)
__device__ uint32_t g_s0[2][BB * HH];        // seq0 ring, packed hi|lo bf16
__device__ uint32_t g_h1[2][BB * HH];        // layer-1 h ring, packed
__device__ float    g_hlast[BB * HH];

__device__ unsigned g_gcnt[8];               // per-bt arrival counters
__device__ unsigned g_ggen[8];               // per-bt generation (monotonic)

// bf16 split weights for the layer-0 input projection GEMM
__device__ __nv_bfloat16 g_w0h[HH * DD], g_w0l[HH * DD];

// ---------------- per-group sense barrier (16 CTAs sharing bt) --------------
__device__ __forceinline__ void grp_bar(int bt) {
    __syncthreads();
    if (threadIdx.x == 0) {
        __threadfence();   // release
        unsigned snap = *(volatile unsigned*)&g_ggen[bt];
        unsigned old = atomicAdd(&g_gcnt[bt], 1u);
        if (old == GRP - 1u) {
            g_gcnt[bt] = 0u;
            __threadfence();
            atomicExch(&g_ggen[bt], snap + 1u);
        } else {
            while (*(volatile unsigned*)&g_ggen[bt] == snap) {}
            __threadfence();  // acquire
        }
    }
    __syncthreads();
}

// ---------------- HMMA plumbing ---------------------------------------------
__device__ __forceinline__ uint32_t s2u(const void* p) {
    uint32_t a;
    asm("{ .reg .u64 t; cvta.to.shared.u64 t, %1; cvt.u32.u64 %0, t; }"
        : "=r"(a) : "l"(p));
    return a;
}
__device__ __forceinline__ void ldm_x4(uint32_t& r0, uint32_t& r1,
                                       uint32_t& r2, uint32_t& r3,
                                       uint32_t addr) {
    asm volatile("ldmatrix.sync.aligned.m8n8.x4.shared.b16 {%0,%1,%2,%3}, [%4];"
                 : "=r"(r0), "=r"(r1), "=r"(r2), "=r"(r3) : "r"(addr));
}
__device__ __forceinline__ void ldm_x2(uint32_t& r0, uint32_t& r1,
                                       uint32_t addr) {
    asm volatile("ldmatrix.sync.aligned.m8n8.x2.shared.b16 {%0,%1}, [%2];"
                 : "=r"(r0), "=r"(r1) : "r"(addr));
}
__device__ __forceinline__ void mma_bf16(float* d, const uint32_t* a,
                                         uint32_t b0, uint32_t b1) {
    asm volatile(
        "mma.sync.aligned.m16n8k16.row.col.f32.bf16.bf16.f32 "
        "{%0,%1,%2,%3}, {%4,%5,%6,%7}, {%8,%9}, {%0,%1,%2,%3};"
        : "+f"(d[0]), "+f"(d[1]), "+f"(d[2]), "+f"(d[3])
        : "r"(a[0]), "r"(a[1]), "r"(a[2]), "r"(a[3]), "r"(b0), "r"(b1));
}
__device__ __forceinline__ uint32_t packsplit(float v) {
    __nv_bfloat16 h = __float2bfloat16(v);
    __nv_bfloat16 l = __float2bfloat16(v - __bfloat162float(h));
    return (uint32_t)__bfloat16_as_ushort(h) |
           ((uint32_t)__bfloat16_as_ushort(l) << 16);
}

// ---------------- weight convert: fp32 -> bf16 hi/lo (layer-0 inproj) -------
__global__ void convert_w0(const float* __restrict__ w0) {
    int i = blockIdx.x * 256 + threadIdx.x;
    if (i < HH * DD) {
        float v = w0[i];
        __nv_bfloat16 h = __float2bfloat16(v);
        g_w0h[i] = h;
        g_w0l[i] = __float2bfloat16(v - __bfloat162float(h));
    }
}

// ---------------- HMMA GEMM: C = A @ W^T + b1 + b2 (layer-0 inproj) ---------
// Split bf16: C = Ah*Wh + Ah*Wl + Al*Wh, fp32 accum.
// Tile 128m x 128n, BK=32, 256 threads (8 warps = 4m x 2n), warp 32m x 64n.
#define HM_AH 0
#define HM_AL 8192
#define HM_WH 16384
#define HM_WL 24576
#define HM_SB 32768          // staged bias: 128 floats
#define HM_TOTAL (32768 + 512)

__global__ __launch_bounds__(256, 2) void gemm_hmma(
    const float* __restrict__ A,
    const __nv_bfloat16* __restrict__ Wh, const __nv_bfloat16* __restrict__ Wl,
    const float* __restrict__ b1, const float* __restrict__ b2,
    float* __restrict__ Cm, int K, int permute)
{
    __shared__ __align__(128) uint8_t sm[HM_TOTAL];
    uint32_t sbase = s2u(sm);

    int tid = threadIdx.x;
    int lane = tid & 31;
    int wid = tid >> 5;
    int wm = wid & 3;
    int wn = wid >> 2;
    int m0 = blockIdx.x * 128;
    int n0 = blockIdx.y * 128;

    if (tid < 128) {
        int n = n0 + tid;
        ((float*)(sm + HM_SB))[tid] = b1[n] + (b2 ? b2[n] : 0.f);
    }

    const float* Ap[4];
#pragma unroll
    for (int it = 0; it < 4; ++it) {
        int idx = tid + it * 256;
        int row = idx >> 3;
        int gm = m0 + row;
        if (permute) {
            int b_ = gm & (BB - 1);
            int t_ = gm >> 8;                  // BB == 256
            Ap[it] = A + ((size_t)b_ * TT + t_) * K;
        } else {
            Ap[it] = A + (size_t)gm * K;
        }
    }

    float acc[2][8][4];
#pragma unroll
    for (int mf = 0; mf < 2; ++mf)
#pragma unroll
        for (int nf = 0; nf < 8; ++nf)
#pragma unroll
            for (int q = 0; q < 4; ++q) acc[mf][nf][q] = 0.f;

    int sub = lane >> 3;
    int r8  = lane & 7;

    int nch = K >> 5;
    for (int c = 0; c < nch; ++c) {
        int kc = c << 5;
        __syncthreads();

#pragma unroll
        for (int it = 0; it < 4; ++it) {
            int idx = tid + it * 256;
            int row = idx >> 3, kq = idx & 7;
            float4 v = *(const float4*)(Ap[it] + kc + kq * 4);
            uint32_t s0 = packsplit(v.x), s1 = packsplit(v.y);
            uint32_t s2 = packsplit(v.z), s3 = packsplit(v.w);
            uint2 hp, lp;
            hp.x = (s0 & 0xffffu) | (s1 << 16);
            hp.y = (s2 & 0xffffu) | (s3 << 16);
            lp.x = (s0 >> 16) | (s1 & 0xffff0000u);
            lp.y = (s2 >> 16) | (s3 & 0xffff0000u);
            int kt = kq >> 1, kcol = (kq & 1) * 4;
            uint32_t off = (uint32_t)(((kt * 16) + (row >> 3)) * 128 +
                                      (row & 7) * 16 + kcol * 2);
            *(uint2*)(sm + HM_AH + off) = hp;
            *(uint2*)(sm + HM_AL + off) = lp;
        }
#pragma unroll
        for (int it = 0; it < 4; ++it) {
            int idx = tid + it * 256;
            int row = idx >> 3, kq = idx & 7;
            size_t go = (size_t)(n0 + row) * K + kc + kq * 4;
            uint2 hv = *(const uint2*)(Wh + go);
            uint2 lv = *(const uint2*)(Wl + go);
            int kt = kq >> 1, kcol = (kq & 1) * 4;
            uint32_t off = (uint32_t)(((kt * 16) + (row >> 3)) * 128 +
                                      (row & 7) * 16 + kcol * 2);
            *(uint2*)(sm + HM_WH + off) = hv;
            *(uint2*)(sm + HM_WL + off) = lv;
        }
        __syncthreads();

#pragma unroll
        for (int s = 0; s < 2; ++s) {
            uint32_t ah[2][4], al[2][4];
#pragma unroll
            for (int mf = 0; mf < 2; ++mf) {
                int mt = wm * 4 + mf * 2 + (sub & 1);
                int kt = s * 2 + (sub >> 1);
                uint32_t ad = sbase + HM_AH +
                              (uint32_t)(((kt * 16) + mt) * 128 + r8 * 16);
                ldm_x4(ah[mf][0], ah[mf][1], ah[mf][2], ah[mf][3], ad);
                ldm_x4(al[mf][0], al[mf][1], al[mf][2], al[mf][3],
                       ad + (HM_AL - HM_AH));
            }
#pragma unroll
            for (int nf = 0; nf < 8; ++nf) {
                int nt = wn * 8 + nf;
                int ktb = s * 2 + (sub & 1);
                uint32_t bd = sbase + HM_WH +
                              (uint32_t)(((ktb * 16) + nt) * 128 + r8 * 16);
                uint32_t bh0, bh1, bl0, bl1;
                ldm_x2(bh0, bh1, bd);
                ldm_x2(bl0, bl1, bd + (HM_WL - HM_WH));
                mma_bf16(acc[0][nf], ah[0], bh0, bh1);
                mma_bf16(acc[1][nf], ah[1], bh0, bh1);
                mma_bf16(acc[0][nf], ah[0], bl0, bl1);
                mma_bf16(acc[1][nf], ah[1], bl0, bl1);
                mma_bf16(acc[0][nf], al[0], bh0, bh1);
                mma_bf16(acc[1][nf], al[1], bh0, bh1);
            }
        }
    }

    const float* sb = (const float*)(sm + HM_SB);
#pragma unroll
    for (int mf = 0; mf < 2; ++mf) {
        int mrow = m0 + wm * 32 + mf * 16 + (lane >> 2);
#pragma unroll
        for (int nf = 0; nf < 8; ++nf) {
            int ncol = wn * 64 + nf * 8 + (lane & 3) * 2;
            float bb0 = sb[ncol], bb1 = sb[ncol + 1];
            float2 v0, v1;
            v0.x = acc[mf][nf][0] + bb0; v0.y = acc[mf][nf][1] + bb1;
            v1.x = acc[mf][nf][2] + bb0; v1.y = acc[mf][nf][3] + bb1;
            *(float2*)(Cm + (size_t)mrow * HH + n0 + ncol) = v0;
            *(float2*)(Cm + (size_t)(mrow + 8) * HH + n0 + ncol) = v1;
        }
    }
}

// ---------------- fused dual-layer persistent recurrence --------------------
// Superstep s (0..TT):
//   seq0[s]  = relu(xp0[s] + seq0[s-1] @ W0hh^T)                (s <= TT-1)
//   h1[s-1]  = relu(seq0[s-1] @ W1ih^T + b1 + h1[s-2] @ W1hh^T) (s >= 1)
// All inputs come from superstep s-1 => ONE barrier per superstep, and the
// seq0[s-1] A-stage is shared by the W0hh and W1ih GEMMs.
// Grid 128 = 8 bt x 16 jt; CTA tile 32b x 32j, full K=512 (R9-proven layout).
// SMEM: W0hh hi/lo 64K | W1hh hi/lo 64K | W1ih bf16 32K | A hi/lo 2x32K.
// A-tile layout: per-kb (k8 block) stride 512 B = 4 row-blocks x 128 B,
// XOR swizzle by kb&7 within row-block (exact R9 scheme — kb*512, NOT 256).
#define FS_W0H 0
#define FS_W0L 32768
#define FS_W1H 65536
#define FS_W1L 98304
#define FS_WIH 131072
#define FS_AH  163840
#define FS_AL  196608
#define FS_TOTAL 229376

__global__ __launch_bounds__(256, 1) void fused_rec(
    const float* __restrict__ xp0,     // [T][B][H]
    const float* __restrict__ W0hh,    // [H][H] fp32
    const float* __restrict__ W1hh,    // [H][H] fp32
    const float* __restrict__ W1ih,    // [H][H] fp32
    const float* __restrict__ b_ih1,
    const float* __restrict__ b_hh1,
    uint32_t* __restrict__ s0ring,     // [2][B][H] packed
    uint32_t* __restrict__ h1ring,     // [2][B][H] packed
    float* __restrict__ h_last)        // [B][H] fp32
{
    extern __shared__ uint8_t sm[];
    uint32_t sb = s2u(sm);

    int cid = blockIdx.x;
    int bt = cid >> 4;                 // 0..7
    int jt = cid & 15;                 // 0..15
    int b0 = bt * 32, j0 = jt * 32;

    int tid = threadIdx.x;
    int lane = tid & 31, wid = tid >> 5;
    int sub = lane >> 3, r8 = lane & 7;
    int mt = wid & 1;                  // 16-row m-tile
    int jb = wid >> 1;                 // 8-col j-block (0..3)

    // ---- preload weight slices (one time) ---------------------------------
    // W0hh, W1hh: hi/lo; W1ih: single bf16. 32 j-rows x 512 k each.
    for (int idx = tid; idx < 4096; idx += 256) {
        int row = idx >> 7, kq = idx & 127;
        int kb = kq >> 1;
        uint32_t off = (uint32_t)kb * 512u + (uint32_t)(row >> 3) * 128u +
                       ((uint32_t)((row & 7) ^ (kb & 7)) << 4) +
                       (uint32_t)(kq & 1) * 8u;
        {
            float4 v = *(const float4*)(W0hh + (size_t)(j0 + row) * HH + kq * 4);
            uint32_t s0 = packsplit(v.x), s1 = packsplit(v.y);
            uint32_t s2 = packsplit(v.z), s3 = packsplit(v.w);
            uint2 hi, lo;
            hi.x = (s0 & 0xffffu) | (s1 << 16);
            hi.y = (s2 & 0xffffu) | (s3 << 16);
            lo.x = (s0 >> 16) | (s1 & 0xffff0000u);
            lo.y = (s2 >> 16) | (s3 & 0xffff0000u);
            *(uint2*)(sm + FS_W0H + off) = hi;
            *(uint2*)(sm + FS_W0L + off) = lo;
        }
        {
            float4 v = *(const float4*)(W1hh + (size_t)(j0 + row) * HH + kq * 4);
            uint32_t s0 = packsplit(v.x), s1 = packsplit(v.y);
            uint32_t s2 = packsplit(v.z), s3 = packsplit(v.w);
            uint2 hi, lo;
            hi.x = (s0 & 0xffffu) | (s1 << 16);
            hi.y = (s2 & 0xffffu) | (s3 << 16);
            lo.x = (s0 >> 16) | (s1 & 0xffff0000u);
            lo.y = (s2 >> 16) | (s3 & 0xffff0000u);
            *(uint2*)(sm + FS_W1H + off) = hi;
            *(uint2*)(sm + FS_W1L + off) = lo;
        }
        {
            float4 v = *(const float4*)(W1ih + (size_t)(j0 + row) * HH + kq * 4);
            __nv_bfloat16 h0 = __float2bfloat16(v.x);
            __nv_bfloat16 h1v = __float2bfloat16(v.y);
            __nv_bfloat16 h2 = __float2bfloat16(v.z);
            __nv_bfloat16 h3 = __float2bfloat16(v.w);
            uint2 hi;
            hi.x = (uint32_t)__bfloat16_as_ushort(h0) |
                   ((uint32_t)__bfloat16_as_ushort(h1v) << 16);
            hi.y = (uint32_t)__bfloat16_as_ushort(h2) |
                   ((uint32_t)__bfloat16_as_ushort(h3) << 16);
            *(uint2*)(sm + FS_WIH + off) = hi;
        }
    }

    // output fragment coordinates (m16n8 D layout)
    int brow = b0 + mt * 16 + (lane >> 2);
    int jcol = j0 + jb * 8 + (lane & 3) * 2;

    // layer-1 bias (depends on j only)
    float2 bias1;
    bias1.x = b_ih1[jcol] + b_hh1[jcol];
    bias1.y = b_ih1[jcol + 1] + b_hh1[jcol + 1];

    __syncthreads();   // weights visible CTA-wide

    for (int s = 0; s <= TT; ++s) {
        const int doL0 = (s < TT);
        const int haveA = (s >= 1);
        const int doHH = (s >= 2);

        float acc0[4] = {0.f, 0.f, 0.f, 0.f};
        float accx[4] = {0.f, 0.f, 0.f, 0.f};

        if (haveA) {
            // ---- stage seq0[s-1] (packed) -> AH/AL (kb*512 layout) -------
            const uint32_t* hsrc = s0ring + (size_t)((s - 1) & 1) * BB * HH;
#pragma unroll
            for (int it = 0; it < 16; ++it) {
                int idx = tid + it * 256;
                int row = idx >> 7, kq = idx & 127;
                uint4 p = *(const uint4*)(hsrc + (size_t)(b0 + row) * HH + kq * 4);
                uint2 hi, lo;
                hi.x = (p.x & 0xffffu) | (p.y << 16);
                hi.y = (p.z & 0xffffu) | (p.w << 16);
                lo.x = (p.x >> 16) | (p.y & 0xffff0000u);
                lo.y = (p.z >> 16) | (p.w & 0xffff0000u);
                int kb = kq >> 1;
                uint32_t off = (uint32_t)kb * 512u +
                               (uint32_t)(row >> 3) * 128u +
                               ((uint32_t)((row & 7) ^ (kb & 7)) << 4) +
                               (uint32_t)(kq & 1) * 8u;
                *(uint2*)(sm + FS_AH + off) = hi;
                *(uint2*)(sm + FS_AL + off) = lo;
            }
            __syncthreads();

            // ---- GEMM 1: acc0 += A @ W0hh (3-pass); accx += A @ W1ih (2) -
#pragma unroll 4
            for (int ks = 0; ks < 32; ++ks) {
                int kbA = ks * 2 + (sub >> 1);
                uint32_t aoff = (uint32_t)kbA * 512u +
                                (uint32_t)(mt * 2 + (sub & 1)) * 128u +
                                ((uint32_t)(r8 ^ (kbA & 7)) << 4);
                uint32_t ah[4], al[4];
                ldm_x4(ah[0], ah[1], ah[2], ah[3], sb + FS_AH + aoff);
                ldm_x4(al[0], al[1], al[2], al[3], sb + FS_AL + aoff);

                int kbB = ks * 2 + (sub & 1);
                uint32_t boff = (uint32_t)kbB * 512u + (uint32_t)jb * 128u +
                                ((uint32_t)(r8 ^ (kbB & 7)) << 4);
                uint32_t bh0, bh1, bl0, bl1, bi0, bi1;
                ldm_x2(bh0, bh1, sb + FS_W0H + boff);
                ldm_x2(bl0, bl1, sb + FS_W0L + boff);
                ldm_x2(bi0, bi1, sb + FS_WIH + boff);

                mma_bf16(acc0, ah, bh0, bh1);
                mma_bf16(acc0, ah, bl0, bl1);
                mma_bf16(acc0, al, bh0, bh1);
                mma_bf16(accx, ah, bi0, bi1);
                mma_bf16(accx, al, bi0, bi1);
            }
            __syncthreads();   // A-region reads complete before re-stage
        }

        // ---- produce + publish seq0[s] -----------------------------------
        if (doL0) {
            const float* xpt = xp0 + (size_t)s * BB * HH;
            float2 x0 = *(const float2*)(xpt + (size_t)brow * HH + jcol);
            float2 x1 = *(const float2*)(xpt + (size_t)(brow + 8) * HH + jcol);
            float v0 = fmaxf(acc0[0] + x0.x, 0.f);
            float v1 = fmaxf(acc0[1] + x0.y, 0.f);
            float v2 = fmaxf(acc0[2] + x1.x, 0.f);
            float v3 = fmaxf(acc0[3] + x1.y, 0.f);
            uint32_t* hdst = s0ring + (size_t)(s & 1) * BB * HH;
            uint2 pa, pb;
            pa.x = packsplit(v0); pa.y = packsplit(v1);
            pb.x = packsplit(v2); pb.y = packsplit(v3);
            *(uint2*)(hdst + (size_t)brow * HH + jcol) = pa;
            *(uint2*)(hdst + (size_t)(brow + 8) * HH + jcol) = pb;
        }

        // ---- GEMM 2: accx += h1[s-2] @ W1hh (3-pass) ---------------------
        if (doHH) {
            const uint32_t* hsrc = h1ring + (size_t)(s & 1) * BB * HH;
#pragma unroll
            for (int it = 0; it < 16; ++it) {
                int idx = tid + it * 256;
                int row = idx >> 7, kq = idx & 127;
                uint4 p = *(const uint4*)(hsrc + (size_t)(b0 + row) * HH + kq * 4);
                uint2 hi, lo;
                hi.x = (p.x & 0xffffu) | (p.y << 16);
                hi.y = (p.z & 0xffffu) | (p.w << 16);
                lo.x = (p.x >> 16) | (p.y & 0xffff0000u);
                lo.y = (p.z >> 16) | (p.w & 0xffff0000u);
                int kb = kq >> 1;
                uint32_t off = (uint32_t)kb * 512u +
                               (uint32_t)(row >> 3) * 128u +
                               ((uint32_t)((row & 7) ^ (kb & 7)) << 4) +
                               (uint32_t)(kq & 1) * 8u;
                *(uint2*)(sm + FS_AH + off) = hi;
                *(uint2*)(sm + FS_AL + off) = lo;
            }
            __syncthreads();

#pragma unroll 4
            for (int ks = 0; ks < 32; ++ks) {
                int kbA = ks * 2 + (sub >> 1);
                uint32_t aoff = (uint32_t)kbA * 512u +
                                (uint32_t)(mt * 2 + (sub & 1)) * 128u +
                                ((uint32_t)(r8 ^ (kbA & 7)) << 4);
                uint32_t ah[4], al[4];
                ldm_x4(ah[0], ah[1], ah[2], ah[3], sb + FS_AH + aoff);
                ldm_x4(al[0], al[1], al[2], al[3], sb + FS_AL + aoff);

                int kbB = ks * 2 + (sub & 1);
                uint32_t boff = (uint32_t)kbB * 512u + (uint32_t)jb * 128u +
                                ((uint32_t)(r8 ^ (kbB & 7)) << 4);
                uint32_t bh0, bh1, bl0, bl1;
                ldm_x2(bh0, bh1, sb + FS_W1H + boff);
                ldm_x2(bl0, bl1, sb + FS_W1L + boff);

                mma_bf16(accx, ah, bh0, bh1);
                mma_bf16(accx, ah, bl0, bl1);
                mma_bf16(accx, al, bh0, bh1);
            }
            __syncthreads();   // A-region free before next superstep
        }

        // ---- produce + publish h1[s-1] -----------------------------------
        if (haveA) {
            float v0 = fmaxf(accx[0] + bias1.x, 0.f);
            float v1 = fmaxf(accx[1] + bias1.y, 0.f);
            float v2 = fmaxf(accx[2] + bias1.x, 0.f);
            float v3 = fmaxf(accx[3] + bias1.y, 0.f);
            uint32_t* hdst = h1ring + (size_t)((s - 1) & 1) * BB * HH;
            uint2 pa, pb;
            pa.x = packsplit(v0); pa.y = packsplit(v1);
            pb.x = packsplit(v2); pb.y = packsplit(v3);
            *(uint2*)(hdst + (size_t)brow * HH + jcol) = pa;
            *(uint2*)(hdst + (size_t)(brow + 8) * HH + jcol) = pb;
            if (s - 1 == TT - 1) {
                *(float2*)(h_last + (size_t)brow * HH + jcol) =
                    make_float2(v0, v1);
                *(float2*)(h_last + (size_t)(brow + 8) * HH + jcol) =
                    make_float2(v2, v3);
            }
        }

        grp_bar(bt);
    }
}

// ---------------- head: relu(h @ fc1^T + b1) @ fc2^T + b2 -------------------
__global__ __launch_bounds__(256) void head_kernel(
    const float* __restrict__ hl, const float* __restrict__ w1,
    const float* __restrict__ b1f, const float* __restrict__ w2,
    const float* __restrict__ b2f, float* __restrict__ out)
{
    __shared__ float sh[8];
    int b = blockIdx.x;
    int tid = threadIdx.x;
    int w = tid >> 5;
    int lane = tid & 31;

    const float* hb = hl + (size_t)b * HH;
    const float* wr = w1 + (size_t)w * HH;
    float ssum = 0.f;
    for (int k = lane; k < HH; k += 32) ssum += hb[k] * wr[k];
#pragma unroll
    for (int o = 16; o; o >>= 1) ssum += __shfl_xor_sync(0xffffffffu, ssum, o);
    if (lane == 0) sh[w] = fmaxf(ssum + b1f[w], 0.f);
    __syncthreads();
    if (tid < OO) {
        float r = b2f[tid];
#pragma unroll
        for (int j = 0; j < 8; ++j) r += sh[j] * w2[tid * 8 + j];
        out[(size_t)b * OO + tid] = r;
    }
}

// ---------------- launch ----------------------------------------------------
extern "C" void kernel_launch(void* const* d_in, const int* in_sizes, int n_in,
                              void* d_out, int out_size)
{
    const float* x     = (const float*)d_in[0];
    const float* w_ih0 = (const float*)d_in[1];
    const float* w_hh0 = (const float*)d_in[2];
    const float* b_ih0 = (const float*)d_in[3];
    const float* b_hh0 = (const float*)d_in[4];
    const float* w_ih1 = (const float*)d_in[5];
    const float* w_hh1 = (const float*)d_in[6];
    const float* b_ih1 = (const float*)d_in[7];
    const float* b_hh1 = (const float*)d_in[8];
    const float* fc1_w = (const float*)d_in[9];
    const float* fc1_b = (const float*)d_in[10];
    const float* fc2_w = (const float*)d_in[11];
    const float* fc2_b = (const float*)d_in[12];
    float* out = (float*)d_out;

    void* p;
    cudaGetSymbolAddress(&p, g_xp0);   float* xp0 = (float*)p;
    cudaGetSymbolAddress(&p, g_s0);    uint32_t* s0ring = (uint32_t*)p;
    cudaGetSymbolAddress(&p, g_h1);    uint32_t* h1ring = (uint32_t*)p;
    cudaGetSymbolAddress(&p, g_hlast); float* hlast = (float*)p;
    cudaGetSymbolAddress(&p, g_w0h);   __nv_bfloat16* w0h = (__nv_bfloat16*)p;
    cudaGetSymbolAddress(&p, g_w0l);   __nv_bfloat16* w0l = (__nv_bfloat16*)p;

    cudaFuncSetAttribute(fused_rec,
                         cudaFuncAttributeMaxDynamicSharedMemorySize,
                         FS_TOTAL);

    dim3 gg(TT * BB / 128, HH / 128);   // 512 x 4

    // layer-0 input projection weights -> bf16 hi/lo
    convert_w0<<<(HH * DD + 255) / 256, 256>>>(w_ih0);
    // layer-0 input projection: xp0 = x @ w_ih0^T + b_ih0 + b_hh0
    gemm_hmma<<<gg, 256>>>(x, w0h, w0l, b_ih0, b_hh0, xp0, DD, 1);
    // fused dual-layer recurrence (replaces rec0 + gemm1 + rec1)
    fused_rec<<<NBLK, 256, FS_TOTAL>>>(xp0, w_hh0, w_hh1, w_ih1,
                                       b_ih1, b_hh1, s0ring, h1ring, hlast);
    // head
    head_kernel<<<BB, 256>>>(hlast, fc1_w, fc1_b, fc2_w, fc2_b, out);
}

// round 13
// speedup vs baseline: 2.5732x; 1.3573x over previous
#include <cuda_runtime.h>
#include <cuda_bf16.h>
#include <cuda_fp16.h>
#include <cstdint>

#define BB 256     // batch
#define TT 256     // time steps
#define DD 64      // input dim
#define HH 512     // hidden
#define OO 10      // output classes

#define NBLK 128   // fused rec grid: 8 bt x 16 jt (all co-resident, 1/SM)
#define GRP  16    // CTAs per bt dependency group
#define HW   (HH / 2)   // ring row stride in uint32 (fp16 pairs)

// ---------------- scratch (static device globals; no allocation allowed) ----
__device__ float    g_xp0[TT * BB * HH];     // [t][b][h] fp32 (layer-0 inproj)
__device__ uint32_t g_s0[2][BB * HW];        // seq0 ring, fp16 pairs
__device__ uint32_t g_h1[2][BB * HW];        // layer-1 h ring, fp16 pairs
__device__ float    g_hlast[BB * HH];

__device__ unsigned g_gcnt[8];               // per-bt arrival counters
__device__ unsigned g_ggen[8];               // per-bt generation (monotonic)

// bf16 split weights for the layer-0 input projection GEMM
__device__ __nv_bfloat16 g_w0h[HH * DD], g_w0l[HH * DD];

// ---------------- per-group sense barrier (16 CTAs sharing bt) --------------
__device__ __forceinline__ void grp_bar(int bt) {
    __syncthreads();
    if (threadIdx.x == 0) {
        __threadfence();   // release
        unsigned snap = *(volatile unsigned*)&g_ggen[bt];
        unsigned old = atomicAdd(&g_gcnt[bt], 1u);
        if (old == GRP - 1u) {
            g_gcnt[bt] = 0u;
            __threadfence();
            atomicExch(&g_ggen[bt], snap + 1u);
        } else {
            while (*(volatile unsigned*)&g_ggen[bt] == snap) {}
            __threadfence();  // acquire
        }
    }
    __syncthreads();
}

// ---------------- MMA plumbing ----------------------------------------------
__device__ __forceinline__ uint32_t s2u(const void* p) {
    uint32_t a;
    asm("{ .reg .u64 t; cvta.to.shared.u64 t, %1; cvt.u32.u64 %0, t; }"
        : "=r"(a) : "l"(p));
    return a;
}
__device__ __forceinline__ void ldm_x4(uint32_t& r0, uint32_t& r1,
                                       uint32_t& r2, uint32_t& r3,
                                       uint32_t addr) {
    asm volatile("ldmatrix.sync.aligned.m8n8.x4.shared.b16 {%0,%1,%2,%3}, [%4];"
                 : "=r"(r0), "=r"(r1), "=r"(r2), "=r"(r3) : "r"(addr));
}
__device__ __forceinline__ void ldm_x2(uint32_t& r0, uint32_t& r1,
                                       uint32_t addr) {
    asm volatile("ldmatrix.sync.aligned.m8n8.x2.shared.b16 {%0,%1}, [%2];"
                 : "=r"(r0), "=r"(r1) : "r"(addr));
}
__device__ __forceinline__ void mma_bf16(float* d, const uint32_t* a,
                                         uint32_t b0, uint32_t b1) {
    asm volatile(
        "mma.sync.aligned.m16n8k16.row.col.f32.bf16.bf16.f32 "
        "{%0,%1,%2,%3}, {%4,%5,%6,%7}, {%8,%9}, {%0,%1,%2,%3};"
        : "+f"(d[0]), "+f"(d[1]), "+f"(d[2]), "+f"(d[3])
        : "r"(a[0]), "r"(a[1]), "r"(a[2]), "r"(a[3]), "r"(b0), "r"(b1));
}
__device__ __forceinline__ void mma_f16(float* d, const uint32_t* a,
                                        uint32_t b0, uint32_t b1) {
    asm volatile(
        "mma.sync.aligned.m16n8k16.row.col.f32.f16.f16.f32 "
        "{%0,%1,%2,%3}, {%4,%5,%6,%7}, {%8,%9}, {%0,%1,%2,%3};"
        : "+f"(d[0]), "+f"(d[1]), "+f"(d[2]), "+f"(d[3])
        : "r"(a[0]), "r"(a[1]), "r"(a[2]), "r"(a[3]), "r"(b0), "r"(b1));
}
__device__ __forceinline__ uint32_t packsplit(float v) {
    __nv_bfloat16 h = __float2bfloat16(v);
    __nv_bfloat16 l = __float2bfloat16(v - __bfloat162float(h));
    return (uint32_t)__bfloat16_as_ushort(h) |
           ((uint32_t)__bfloat16_as_ushort(l) << 16);
}
__device__ __forceinline__ uint32_t packh2(float lo, float hi) {
    __half2 h = __floats2half2_rn(lo, hi);   // .x = lo (low 16 bits)
    uint32_t u;
    asm("mov.b32 %0, %1;" : "=r"(u) : "r"(*(uint32_t*)&h));
    return u;
}

// ---------------- weight convert: fp32 -> bf16 hi/lo (layer-0 inproj) -------
__global__ void convert_w0(const float* __restrict__ w0) {
    int i = blockIdx.x * 256 + threadIdx.x;
    if (i < HH * DD) {
        float v = w0[i];
        __nv_bfloat16 h = __float2bfloat16(v);
        g_w0h[i] = h;
        g_w0l[i] = __float2bfloat16(v - __bfloat162float(h));
    }
}

// ---------------- HMMA GEMM: C = A @ W^T + b1 + b2 (layer-0 inproj) ---------
// Split bf16: C = Ah*Wh + Ah*Wl + Al*Wh, fp32 accum. (R8-proven, unchanged.)
#define HM_AH 0
#define HM_AL 8192
#define HM_WH 16384
#define HM_WL 24576
#define HM_SB 32768
#define HM_TOTAL (32768 + 512)

__global__ __launch_bounds__(256, 2) void gemm_hmma(
    const float* __restrict__ A,
    const __nv_bfloat16* __restrict__ Wh, const __nv_bfloat16* __restrict__ Wl,
    const float* __restrict__ b1, const float* __restrict__ b2,
    float* __restrict__ Cm, int K, int permute)
{
    __shared__ __align__(128) uint8_t sm[HM_TOTAL];
    uint32_t sbase = s2u(sm);

    int tid = threadIdx.x;
    int lane = tid & 31;
    int wid = tid >> 5;
    int wm = wid & 3;
    int wn = wid >> 2;
    int m0 = blockIdx.x * 128;
    int n0 = blockIdx.y * 128;

    if (tid < 128) {
        int n = n0 + tid;
        ((float*)(sm + HM_SB))[tid] = b1[n] + (b2 ? b2[n] : 0.f);
    }

    const float* Ap[4];
#pragma unroll
    for (int it = 0; it < 4; ++it) {
        int idx = tid + it * 256;
        int row = idx >> 3;
        int gm = m0 + row;
        if (permute) {
            int b_ = gm & (BB - 1);
            int t_ = gm >> 8;                  // BB == 256
            Ap[it] = A + ((size_t)b_ * TT + t_) * K;
        } else {
            Ap[it] = A + (size_t)gm * K;
        }
    }

    float acc[2][8][4];
#pragma unroll
    for (int mf = 0; mf < 2; ++mf)
#pragma unroll
        for (int nf = 0; nf < 8; ++nf)
#pragma unroll
            for (int q = 0; q < 4; ++q) acc[mf][nf][q] = 0.f;

    int sub = lane >> 3;
    int r8  = lane & 7;

    int nch = K >> 5;
    for (int c = 0; c < nch; ++c) {
        int kc = c << 5;
        __syncthreads();

#pragma unroll
        for (int it = 0; it < 4; ++it) {
            int idx = tid + it * 256;
            int row = idx >> 3, kq = idx & 7;
            float4 v = *(const float4*)(Ap[it] + kc + kq * 4);
            uint32_t s0 = packsplit(v.x), s1 = packsplit(v.y);
            uint32_t s2 = packsplit(v.z), s3 = packsplit(v.w);
            uint2 hp, lp;
            hp.x = (s0 & 0xffffu) | (s1 << 16);
            hp.y = (s2 & 0xffffu) | (s3 << 16);
            lp.x = (s0 >> 16) | (s1 & 0xffff0000u);
            lp.y = (s2 >> 16) | (s3 & 0xffff0000u);
            int kt = kq >> 1, kcol = (kq & 1) * 4;
            uint32_t off = (uint32_t)(((kt * 16) + (row >> 3)) * 128 +
                                      (row & 7) * 16 + kcol * 2);
            *(uint2*)(sm + HM_AH + off) = hp;
            *(uint2*)(sm + HM_AL + off) = lp;
        }
#pragma unroll
        for (int it = 0; it < 4; ++it) {
            int idx = tid + it * 256;
            int row = idx >> 3, kq = idx & 7;
            size_t go = (size_t)(n0 + row) * K + kc + kq * 4;
            uint2 hv = *(const uint2*)(Wh + go);
            uint2 lv = *(const uint2*)(Wl + go);
            int kt = kq >> 1, kcol = (kq & 1) * 4;
            uint32_t off = (uint32_t)(((kt * 16) + (row >> 3)) * 128 +
                                      (row & 7) * 16 + kcol * 2);
            *(uint2*)(sm + HM_WH + off) = hv;
            *(uint2*)(sm + HM_WL + off) = lv;
        }
        __syncthreads();

#pragma unroll
        for (int s = 0; s < 2; ++s) {
            uint32_t ah[2][4], al[2][4];
#pragma unroll
            for (int mf = 0; mf < 2; ++mf) {
                int mt = wm * 4 + mf * 2 + (sub & 1);
                int kt = s * 2 + (sub >> 1);
                uint32_t ad = sbase + HM_AH +
                              (uint32_t)(((kt * 16) + mt) * 128 + r8 * 16);
                ldm_x4(ah[mf][0], ah[mf][1], ah[mf][2], ah[mf][3], ad);
                ldm_x4(al[mf][0], al[mf][1], al[mf][2], al[mf][3],
                       ad + (HM_AL - HM_AH));
            }
#pragma unroll
            for (int nf = 0; nf < 8; ++nf) {
                int nt = wn * 8 + nf;
                int ktb = s * 2 + (sub & 1);
                uint32_t bd = sbase + HM_WH +
                              (uint32_t)(((ktb * 16) + nt) * 128 + r8 * 16);
                uint32_t bh0, bh1, bl0, bl1;
                ldm_x2(bh0, bh1, bd);
                ldm_x2(bl0, bl1, bd + (HM_WL - HM_WH));
                mma_bf16(acc[0][nf], ah[0], bh0, bh1);
                mma_bf16(acc[1][nf], ah[1], bh0, bh1);
                mma_bf16(acc[0][nf], ah[0], bl0, bl1);
                mma_bf16(acc[1][nf], ah[1], bl0, bl1);
                mma_bf16(acc[0][nf], al[0], bh0, bh1);
                mma_bf16(acc[1][nf], al[1], bh0, bh1);
            }
        }
    }

    const float* sb = (const float*)(sm + HM_SB);
#pragma unroll
    for (int mf = 0; mf < 2; ++mf) {
        int mrow = m0 + wm * 32 + mf * 16 + (lane >> 2);
#pragma unroll
        for (int nf = 0; nf < 8; ++nf) {
            int ncol = wn * 64 + nf * 8 + (lane & 3) * 2;
            float bb0 = sb[ncol], bb1 = sb[ncol + 1];
            float2 v0, v1;
            v0.x = acc[mf][nf][0] + bb0; v0.y = acc[mf][nf][1] + bb1;
            v1.x = acc[mf][nf][2] + bb0; v1.y = acc[mf][nf][3] + bb1;
            *(float2*)(Cm + (size_t)mrow * HH + n0 + ncol) = v0;
            *(float2*)(Cm + (size_t)(mrow + 8) * HH + n0 + ncol) = v1;
        }
    }
}

// ---------------- fused dual-layer persistent recurrence (fp16) -------------
// Superstep s (0..TT):
//   seq0[s]  = relu(xp0[s] + seq0[s-1] @ W0hh^T)                (s <= TT-1)
//   h1[s-1]  = relu(seq0[s-1] @ W1ih^T + b1 + h1[s-2] @ W1hh^T) (s >= 1)
// Activations fp16 (single copy); W0hh/W1hh fp16 hi/lo (2-pass); W1ih fp16
// (1-pass). Both A-tiles staged together -> ONE syncthreads + ONE barrier
// per superstep; merged 5-MMA ks loop.
// A/W layout: per-k8-block kb stride 512 B = 4 row-blocks x 128 B, row
// XOR-swizzled by kb&7 (R9-proven addressing, kb*512).
#define FS_W0H 0
#define FS_W0L 32768
#define FS_W1H 65536
#define FS_W1L 98304
#define FS_WIH 131072
#define FS_A1  163840
#define FS_A2  196608
#define FS_TOTAL 229376

__global__ __launch_bounds__(256, 1) void fused_rec(
    const float* __restrict__ xp0,     // [T][B][H]
    const float* __restrict__ W0hh,    // [H][H] fp32
    const float* __restrict__ W1hh,    // [H][H] fp32
    const float* __restrict__ W1ih,    // [H][H] fp32
    const float* __restrict__ b_ih1,
    const float* __restrict__ b_hh1,
    uint32_t* __restrict__ s0ring,     // [2][B][HW] fp16 pairs
    uint32_t* __restrict__ h1ring,     // [2][B][HW] fp16 pairs
    float* __restrict__ h_last)        // [B][H] fp32
{
    extern __shared__ uint8_t sm[];
    uint32_t sb = s2u(sm);

    int cid = blockIdx.x;
    int bt = cid >> 4;                 // 0..7
    int jt = cid & 15;                 // 0..15
    int b0 = bt * 32, j0 = jt * 32;

    int tid = threadIdx.x;
    int lane = tid & 31, wid = tid >> 5;
    int sub = lane >> 3, r8 = lane & 7;
    int mt = wid & 1;                  // 16-row m-tile
    int jb = wid >> 1;                 // 8-col j-block (0..3)

    // ---- preload weight slices (one time): fp16 hi/lo + fp16 W1ih ---------
    for (int idx = tid; idx < 4096; idx += 256) {
        int row = idx >> 7, kq = idx & 127;          // kq: 4-elem group
        int kb = kq >> 1;
        uint32_t off = (uint32_t)kb * 512u + (uint32_t)(row >> 3) * 128u +
                       ((uint32_t)((row & 7) ^ (kb & 7)) << 4) +
                       (uint32_t)(kq & 1) * 8u;
        {
            float4 v = *(const float4*)(W0hh + (size_t)(j0 + row) * HH + kq * 4);
            __half hx = __float2half_rn(v.x), hy = __float2half_rn(v.y);
            __half hz = __float2half_rn(v.z), hw = __float2half_rn(v.w);
            uint2 hi, lo;
            hi.x = packh2(__half2float(hx), 0.f) |
                   (packh2(__half2float(hy), 0.f) << 16);
            // build directly from bit patterns instead:
            hi.x = (uint32_t)__half_as_ushort(hx) |
                   ((uint32_t)__half_as_ushort(hy) << 16);
            hi.y = (uint32_t)__half_as_ushort(hz) |
                   ((uint32_t)__half_as_ushort(hw) << 16);
            __half lx = __float2half_rn(v.x - __half2float(hx));
            __half ly = __float2half_rn(v.y - __half2float(hy));
            __half lz = __float2half_rn(v.z - __half2float(hz));
            __half lw = __float2half_rn(v.w - __half2float(hw));
            lo.x = (uint32_t)__half_as_ushort(lx) |
                   ((uint32_t)__half_as_ushort(ly) << 16);
            lo.y = (uint32_t)__half_as_ushort(lz) |
                   ((uint32_t)__half_as_ushort(lw) << 16);
            *(uint2*)(sm + FS_W0H + off) = hi;
            *(uint2*)(sm + FS_W0L + off) = lo;
        }
        {
            float4 v = *(const float4*)(W1hh + (size_t)(j0 + row) * HH + kq * 4);
            __half hx = __float2half_rn(v.x), hy = __float2half_rn(v.y);
            __half hz = __float2half_rn(v.z), hw = __float2half_rn(v.w);
            uint2 hi, lo;
            hi.x = (uint32_t)__half_as_ushort(hx) |
                   ((uint32_t)__half_as_ushort(hy) << 16);
            hi.y = (uint32_t)__half_as_ushort(hz) |
                   ((uint32_t)__half_as_ushort(hw) << 16);
            __half lx = __float2half_rn(v.x - __half2float(hx));
            __half ly = __float2half_rn(v.y - __half2float(hy));
            __half lz = __float2half_rn(v.z - __half2float(hz));
            __half lw = __float2half_rn(v.w - __half2float(hw));
            lo.x = (uint32_t)__half_as_ushort(lx) |
                   ((uint32_t)__half_as_ushort(ly) << 16);
            lo.y = (uint32_t)__half_as_ushort(lz) |
                   ((uint32_t)__half_as_ushort(lw) << 16);
            *(uint2*)(sm + FS_W1H + off) = hi;
            *(uint2*)(sm + FS_W1L + off) = lo;
        }
        {
            float4 v = *(const float4*)(W1ih + (size_t)(j0 + row) * HH + kq * 4);
            uint2 hi;
            hi.x = (uint32_t)__half_as_ushort(__float2half_rn(v.x)) |
                   ((uint32_t)__half_as_ushort(__float2half_rn(v.y)) << 16);
            hi.y = (uint32_t)__half_as_ushort(__float2half_rn(v.z)) |
                   ((uint32_t)__half_as_ushort(__float2half_rn(v.w)) << 16);
            *(uint2*)(sm + FS_WIH + off) = hi;
        }
    }

    // output fragment coordinates (m16n8 D layout)
    int brow = b0 + mt * 16 + (lane >> 2);
    int jcol = j0 + jb * 8 + (lane & 3) * 2;

    float2 bias1;
    bias1.x = b_ih1[jcol] + b_hh1[jcol];
    bias1.y = b_ih1[jcol + 1] + b_hh1[jcol + 1];

    __syncthreads();   // weights visible CTA-wide

    for (int s = 0; s <= TT; ++s) {
        const int doL0 = (s < TT);
        const int haveA = (s >= 1);
        const int doHH = (s >= 2);

        float acc0[4] = {0.f, 0.f, 0.f, 0.f};
        float accx[4] = {0.f, 0.f, 0.f, 0.f};

        if (haveA) {
            // ---- stage BOTH A-tiles (straight swizzled uint4 copies) -----
            {
                const uint32_t* hsrc = s0ring + (size_t)((s - 1) & 1) * BB * HW;
#pragma unroll
                for (int it = 0; it < 8; ++it) {
                    int idx = tid + it * 256;
                    int row = idx >> 6, kb = idx & 63;
                    uint4 p = *(const uint4*)(hsrc + (size_t)(b0 + row) * HW +
                                              kb * 4);
                    uint32_t off = (uint32_t)kb * 512u +
                                   (uint32_t)(row >> 3) * 128u +
                                   ((uint32_t)((row & 7) ^ (kb & 7)) << 4);
                    *(uint4*)(sm + FS_A1 + off) = p;
                }
            }
            if (doHH) {
                const uint32_t* hsrc = h1ring + (size_t)(s & 1) * BB * HW;
#pragma unroll
                for (int it = 0; it < 8; ++it) {
                    int idx = tid + it * 256;
                    int row = idx >> 6, kb = idx & 63;
                    uint4 p = *(const uint4*)(hsrc + (size_t)(b0 + row) * HW +
                                              kb * 4);
                    uint32_t off = (uint32_t)kb * 512u +
                                   (uint32_t)(row >> 3) * 128u +
                                   ((uint32_t)((row & 7) ^ (kb & 7)) << 4);
                    *(uint4*)(sm + FS_A2 + off) = p;
                }
            }
            __syncthreads();

            // ---- merged 5-MMA ks loop ------------------------------------
#pragma unroll 4
            for (int ks = 0; ks < 32; ++ks) {
                int kbA = ks * 2 + (sub >> 1);
                uint32_t aoff = (uint32_t)kbA * 512u +
                                (uint32_t)(mt * 2 + (sub & 1)) * 128u +
                                ((uint32_t)(r8 ^ (kbA & 7)) << 4);
                uint32_t a1[4], a2[4];
                ldm_x4(a1[0], a1[1], a1[2], a1[3], sb + FS_A1 + aoff);
                ldm_x4(a2[0], a2[1], a2[2], a2[3], sb + FS_A2 + aoff);

                int kbB = ks * 2 + (sub & 1);
                uint32_t boff = (uint32_t)kbB * 512u + (uint32_t)jb * 128u +
                                ((uint32_t)(r8 ^ (kbB & 7)) << 4);
                uint32_t w0h0, w0h1, w0l0, w0l1, wi0, wi1;
                uint32_t w1h0, w1h1, w1l0, w1l1;
                ldm_x2(w0h0, w0h1, sb + FS_W0H + boff);
                ldm_x2(w0l0, w0l1, sb + FS_W0L + boff);
                ldm_x2(wi0, wi1, sb + FS_WIH + boff);
                ldm_x2(w1h0, w1h1, sb + FS_W1H + boff);
                ldm_x2(w1l0, w1l1, sb + FS_W1L + boff);

                if (doL0) {
                    mma_f16(acc0, a1, w0h0, w0h1);
                    mma_f16(acc0, a1, w0l0, w0l1);
                }
                mma_f16(accx, a1, wi0, wi1);
                if (doHH) {
                    mma_f16(accx, a2, w1h0, w1h1);
                    mma_f16(accx, a2, w1l0, w1l1);
                }
            }
        }

        // ---- produce + publish seq0[s] -----------------------------------
        if (doL0) {
            const float* xpt = xp0 + (size_t)s * BB * HH;
            float2 x0 = *(const float2*)(xpt + (size_t)brow * HH + jcol);
            float2 x1 = *(const float2*)(xpt + (size_t)(brow + 8) * HH + jcol);
            float v0 = fmaxf(acc0[0] + x0.x, 0.f);
            float v1 = fmaxf(acc0[1] + x0.y, 0.f);
            float v2 = fmaxf(acc0[2] + x1.x, 0.f);
            float v3 = fmaxf(acc0[3] + x1.y, 0.f);
            uint32_t* hdst = s0ring + (size_t)(s & 1) * BB * HW;
            hdst[(size_t)brow * HW + (jcol >> 1)] = packh2(v0, v1);
            hdst[(size_t)(brow + 8) * HW + (jcol >> 1)] = packh2(v2, v3);
        }

        // ---- produce + publish h1[s-1] -----------------------------------
        if (haveA) {
            float v0 = fmaxf(accx[0] + bias1.x, 0.f);
            float v1 = fmaxf(accx[1] + bias1.y, 0.f);
            float v2 = fmaxf(accx[2] + bias1.x, 0.f);
            float v3 = fmaxf(accx[3] + bias1.y, 0.f);
            uint32_t* hdst = h1ring + (size_t)((s - 1) & 1) * BB * HW;
            hdst[(size_t)brow * HW + (jcol >> 1)] = packh2(v0, v1);
            hdst[(size_t)(brow + 8) * HW + (jcol >> 1)] = packh2(v2, v3);
            if (s - 1 == TT - 1) {
                *(float2*)(h_last + (size_t)brow * HH + jcol) =
                    make_float2(v0, v1);
                *(float2*)(h_last + (size_t)(brow + 8) * HH + jcol) =
                    make_float2(v2, v3);
            }
        }

        // barrier: publishes rings group-wide; its internal __syncthreads
        // also orders this step's smem MMA reads before next step's staging.
        grp_bar(bt);
    }
}

// ---------------- head: relu(h @ fc1^T + b1) @ fc2^T + b2 -------------------
__global__ __launch_bounds__(256) void head_kernel(
    const float* __restrict__ hl, const float* __restrict__ w1,
    const float* __restrict__ b1f, const float* __restrict__ w2,
    const float* __restrict__ b2f, float* __restrict__ out)
{
    __shared__ float sh[8];
    int b = blockIdx.x;
    int tid = threadIdx.x;
    int w = tid >> 5;
    int lane = tid & 31;

    const float* hb = hl + (size_t)b * HH;
    const float* wr = w1 + (size_t)w * HH;
    float ssum = 0.f;
    for (int k = lane; k < HH; k += 32) ssum += hb[k] * wr[k];
#pragma unroll
    for (int o = 16; o; o >>= 1) ssum += __shfl_xor_sync(0xffffffffu, ssum, o);
    if (lane == 0) sh[w] = fmaxf(ssum + b1f[w], 0.f);
    __syncthreads();
    if (tid < OO) {
        float r = b2f[tid];
#pragma unroll
        for (int j = 0; j < 8; ++j) r += sh[j] * w2[tid * 8 + j];
        out[(size_t)b * OO + tid] = r;
    }
}

// ---------------- launch ----------------------------------------------------
extern "C" void kernel_launch(void* const* d_in, const int* in_sizes, int n_in,
                              void* d_out, int out_size)
{
    const float* x     = (const float*)d_in[0];
    const float* w_ih0 = (const float*)d_in[1];
    const float* w_hh0 = (const float*)d_in[2];
    const float* b_ih0 = (const float*)d_in[3];
    const float* b_hh0 = (const float*)d_in[4];
    const float* w_ih1 = (const float*)d_in[5];
    const float* w_hh1 = (const float*)d_in[6];
    const float* b_ih1 = (const float*)d_in[7];
    const float* b_hh1 = (const float*)d_in[8];
    const float* fc1_w = (const float*)d_in[9];
    const float* fc1_b = (const float*)d_in[10];
    const float* fc2_w = (const float*)d_in[11];
    const float* fc2_b = (const float*)d_in[12];
    float* out = (float*)d_out;

    void* p;
    cudaGetSymbolAddress(&p, g_xp0);   float* xp0 = (float*)p;
    cudaGetSymbolAddress(&p, g_s0);    uint32_t* s0ring = (uint32_t*)p;
    cudaGetSymbolAddress(&p, g_h1);    uint32_t* h1ring = (uint32_t*)p;
    cudaGetSymbolAddress(&p, g_hlast); float* hlast = (float*)p;
    cudaGetSymbolAddress(&p, g_w0h);   __nv_bfloat16* w0h = (__nv_bfloat16*)p;
    cudaGetSymbolAddress(&p, g_w0l);   __nv_bfloat16* w0l = (__nv_bfloat16*)p;

    cudaFuncSetAttribute(fused_rec,
                         cudaFuncAttributeMaxDynamicSharedMemorySize,
                         FS_TOTAL);

    dim3 gg(TT * BB / 128, HH / 128);   // 512 x 4

    // layer-0 input projection weights -> bf16 hi/lo
    convert_w0<<<(HH * DD + 255) / 256, 256>>>(w_ih0);
    // layer-0 input projection: xp0 = x @ w_ih0^T + b_ih0 + b_hh0
    gemm_hmma<<<gg, 256>>>(x, w0h, w0l, b_ih0, b_hh0, xp0, DD, 1);
    // fused dual-layer recurrence (fp16 activations, merged phases)
    fused_rec<<<NBLK, 256, FS_TOTAL>>>(xp0, w_hh0, w_hh1, w_ih1,
                                       b_ih1, b_hh1, s0ring, h1ring, hlast);
    // head
    head_kernel<<<BB, 256>>>(hlast, fc1_w, fc1_b, fc2_w, fc2_b, out);
}

// round 14
// speedup vs baseline: 2.9225x; 1.1358x over previous
#include <cuda_runtime.h>
#include <cuda_bf16.h>
#include <cuda_fp16.h>
#include <cstdint>

#define BB 256     // batch
#define TT 256     // time steps
#define DD 64      // input dim
#define HH 512     // hidden
#define OO 10      // output classes

#define NBLK 128   // fused rec grid: 8 bt x 16 jt (all co-resident, 1/SM)
#define GRP  16    // CTAs per bt dependency group
#define HW   (HH / 2)   // ring row stride in uint32 (fp16 pairs)

// ---------------- scratch (static device globals; no allocation allowed) ----
__device__ float    g_xp0[TT * BB * HH];     // [t][b][h] fp32 (layer-0 inproj)
__device__ uint32_t g_s0[2][BB * HW];        // seq0 ring, fp16 pairs
__device__ uint32_t g_h1[2][BB * HW];        // layer-1 h ring, fp16 pairs
__device__ float    g_hlast[BB * HH];

__device__ unsigned g_gcnt[8];               // per-bt arrival counters
__device__ unsigned g_ggen[8];               // per-bt generation (monotonic)

// bf16 split weights for the layer-0 input projection GEMM
__device__ __nv_bfloat16 g_w0h[HH * DD], g_w0l[HH * DD];

// ---------------- per-group sense barrier (16 CTAs sharing bt) --------------
__device__ __forceinline__ void grp_bar(int bt) {
    __syncthreads();
    if (threadIdx.x == 0) {
        __threadfence();   // release
        unsigned snap = *(volatile unsigned*)&g_ggen[bt];
        unsigned old = atomicAdd(&g_gcnt[bt], 1u);
        if (old == GRP - 1u) {
            g_gcnt[bt] = 0u;
            __threadfence();
            atomicExch(&g_ggen[bt], snap + 1u);
        } else {
            while (*(volatile unsigned*)&g_ggen[bt] == snap) {}
            __threadfence();  // acquire
        }
    }
    __syncthreads();
}

// ---------------- MMA plumbing ----------------------------------------------
__device__ __forceinline__ uint32_t s2u(const void* p) {
    uint32_t a;
    asm("{ .reg .u64 t; cvta.to.shared.u64 t, %1; cvt.u32.u64 %0, t; }"
        : "=r"(a) : "l"(p));
    return a;
}
__device__ __forceinline__ void ldm_x4(uint32_t& r0, uint32_t& r1,
                                       uint32_t& r2, uint32_t& r3,
                                       uint32_t addr) {
    asm volatile("ldmatrix.sync.aligned.m8n8.x4.shared.b16 {%0,%1,%2,%3}, [%4];"
                 : "=r"(r0), "=r"(r1), "=r"(r2), "=r"(r3) : "r"(addr));
}
__device__ __forceinline__ void ldm_x2(uint32_t& r0, uint32_t& r1,
                                       uint32_t addr) {
    asm volatile("ldmatrix.sync.aligned.m8n8.x2.shared.b16 {%0,%1}, [%2];"
                 : "=r"(r0), "=r"(r1) : "r"(addr));
}
__device__ __forceinline__ void mma_bf16(float* d, const uint32_t* a,
                                         uint32_t b0, uint32_t b1) {
    asm volatile(
        "mma.sync.aligned.m16n8k16.row.col.f32.bf16.bf16.f32 "
        "{%0,%1,%2,%3}, {%4,%5,%6,%7}, {%8,%9}, {%0,%1,%2,%3};"
        : "+f"(d[0]), "+f"(d[1]), "+f"(d[2]), "+f"(d[3])
        : "r"(a[0]), "r"(a[1]), "r"(a[2]), "r"(a[3]), "r"(b0), "r"(b1));
}
__device__ __forceinline__ void mma_f16(float* d, const uint32_t* a,
                                        uint32_t b0, uint32_t b1) {
    asm volatile(
        "mma.sync.aligned.m16n8k16.row.col.f32.f16.f16.f32 "
        "{%0,%1,%2,%3}, {%4,%5,%6,%7}, {%8,%9}, {%0,%1,%2,%3};"
        : "+f"(d[0]), "+f"(d[1]), "+f"(d[2]), "+f"(d[3])
        : "r"(a[0]), "r"(a[1]), "r"(a[2]), "r"(a[3]), "r"(b0), "r"(b1));
}
__device__ __forceinline__ uint32_t packsplit(float v) {
    __nv_bfloat16 h = __float2bfloat16(v);
    __nv_bfloat16 l = __float2bfloat16(v - __bfloat162float(h));
    return (uint32_t)__bfloat16_as_ushort(h) |
           ((uint32_t)__bfloat16_as_ushort(l) << 16);
}
__device__ __forceinline__ uint32_t packh2(float lo, float hi) {
    __half2 h = __floats2half2_rn(lo, hi);   // .x = lo (low 16 bits)
    uint32_t u;
    asm("mov.b32 %0, %1;" : "=r"(u) : "r"(*(uint32_t*)&h));
    return u;
}
__device__ __forceinline__ uint32_t packh2f4lo(float x, float y) {
    return (uint32_t)__half_as_ushort(__float2half_rn(x)) |
           ((uint32_t)__half_as_ushort(__float2half_rn(y)) << 16);
}

// ---------------- weight convert: fp32 -> bf16 hi/lo (layer-0 inproj) -------
__global__ void convert_w0(const float* __restrict__ w0) {
    int i = blockIdx.x * 256 + threadIdx.x;
    if (i < HH * DD) {
        float v = w0[i];
        __nv_bfloat16 h = __float2bfloat16(v);
        g_w0h[i] = h;
        g_w0l[i] = __float2bfloat16(v - __bfloat162float(h));
    }
}

// ---------------- HMMA GEMM: C = A @ W^T + b1 + b2 (layer-0 inproj) ---------
// Split bf16: C = Ah*Wh + Ah*Wl + Al*Wh, fp32 accum. (R8-proven, unchanged.)
#define HM_AH 0
#define HM_AL 8192
#define HM_WH 16384
#define HM_WL 24576
#define HM_SB 32768
#define HM_TOTAL (32768 + 512)

__global__ __launch_bounds__(256, 2) void gemm_hmma(
    const float* __restrict__ A,
    const __nv_bfloat16* __restrict__ Wh, const __nv_bfloat16* __restrict__ Wl,
    const float* __restrict__ b1, const float* __restrict__ b2,
    float* __restrict__ Cm, int K, int permute)
{
    __shared__ __align__(128) uint8_t sm[HM_TOTAL];
    uint32_t sbase = s2u(sm);

    int tid = threadIdx.x;
    int lane = tid & 31;
    int wid = tid >> 5;
    int wm = wid & 3;
    int wn = wid >> 2;
    int m0 = blockIdx.x * 128;
    int n0 = blockIdx.y * 128;

    if (tid < 128) {
        int n = n0 + tid;
        ((float*)(sm + HM_SB))[tid] = b1[n] + (b2 ? b2[n] : 0.f);
    }

    const float* Ap[4];
#pragma unroll
    for (int it = 0; it < 4; ++it) {
        int idx = tid + it * 256;
        int row = idx >> 3;
        int gm = m0 + row;
        if (permute) {
            int b_ = gm & (BB - 1);
            int t_ = gm >> 8;                  // BB == 256
            Ap[it] = A + ((size_t)b_ * TT + t_) * K;
        } else {
            Ap[it] = A + (size_t)gm * K;
        }
    }

    float acc[2][8][4];
#pragma unroll
    for (int mf = 0; mf < 2; ++mf)
#pragma unroll
        for (int nf = 0; nf < 8; ++nf)
#pragma unroll
            for (int q = 0; q < 4; ++q) acc[mf][nf][q] = 0.f;

    int sub = lane >> 3;
    int r8  = lane & 7;

    int nch = K >> 5;
    for (int c = 0; c < nch; ++c) {
        int kc = c << 5;
        __syncthreads();

#pragma unroll
        for (int it = 0; it < 4; ++it) {
            int idx = tid + it * 256;
            int row = idx >> 3, kq = idx & 7;
            float4 v = *(const float4*)(Ap[it] + kc + kq * 4);
            uint32_t s0 = packsplit(v.x), s1 = packsplit(v.y);
            uint32_t s2 = packsplit(v.z), s3 = packsplit(v.w);
            uint2 hp, lp;
            hp.x = (s0 & 0xffffu) | (s1 << 16);
            hp.y = (s2 & 0xffffu) | (s3 << 16);
            lp.x = (s0 >> 16) | (s1 & 0xffff0000u);
            lp.y = (s2 >> 16) | (s3 & 0xffff0000u);
            int kt = kq >> 1, kcol = (kq & 1) * 4;
            uint32_t off = (uint32_t)(((kt * 16) + (row >> 3)) * 128 +
                                      (row & 7) * 16 + kcol * 2);
            *(uint2*)(sm + HM_AH + off) = hp;
            *(uint2*)(sm + HM_AL + off) = lp;
        }
#pragma unroll
        for (int it = 0; it < 4; ++it) {
            int idx = tid + it * 256;
            int row = idx >> 3, kq = idx & 7;
            size_t go = (size_t)(n0 + row) * K + kc + kq * 4;
            uint2 hv = *(const uint2*)(Wh + go);
            uint2 lv = *(const uint2*)(Wl + go);
            int kt = kq >> 1, kcol = (kq & 1) * 4;
            uint32_t off = (uint32_t)(((kt * 16) + (row >> 3)) * 128 +
                                      (row & 7) * 16 + kcol * 2);
            *(uint2*)(sm + HM_WH + off) = hv;
            *(uint2*)(sm + HM_WL + off) = lv;
        }
        __syncthreads();

#pragma unroll
        for (int s = 0; s < 2; ++s) {
            uint32_t ah[2][4], al[2][4];
#pragma unroll
            for (int mf = 0; mf < 2; ++mf) {
                int mt = wm * 4 + mf * 2 + (sub & 1);
                int kt = s * 2 + (sub >> 1);
                uint32_t ad = sbase + HM_AH +
                              (uint32_t)(((kt * 16) + mt) * 128 + r8 * 16);
                ldm_x4(ah[mf][0], ah[mf][1], ah[mf][2], ah[mf][3], ad);
                ldm_x4(al[mf][0], al[mf][1], al[mf][2], al[mf][3],
                       ad + (HM_AL - HM_AH));
            }
#pragma unroll
            for (int nf = 0; nf < 8; ++nf) {
                int nt = wn * 8 + nf;
                int ktb = s * 2 + (sub & 1);
                uint32_t bd = sbase + HM_WH +
                              (uint32_t)(((ktb * 16) + nt) * 128 + r8 * 16);
                uint32_t bh0, bh1, bl0, bl1;
                ldm_x2(bh0, bh1, bd);
                ldm_x2(bl0, bl1, bd + (HM_WL - HM_WH));
                mma_bf16(acc[0][nf], ah[0], bh0, bh1);
                mma_bf16(acc[1][nf], ah[1], bh0, bh1);
                mma_bf16(acc[0][nf], ah[0], bl0, bl1);
                mma_bf16(acc[1][nf], ah[1], bl0, bl1);
                mma_bf16(acc[0][nf], al[0], bh0, bh1);
                mma_bf16(acc[1][nf], al[1], bh0, bh1);
            }
        }
    }

    const float* sb = (const float*)(sm + HM_SB);
#pragma unroll
    for (int mf = 0; mf < 2; ++mf) {
        int mrow = m0 + wm * 32 + mf * 16 + (lane >> 2);
#pragma unroll
        for (int nf = 0; nf < 8; ++nf) {
            int ncol = wn * 64 + nf * 8 + (lane & 3) * 2;
            float bb0 = sb[ncol], bb1 = sb[ncol + 1];
            float2 v0, v1;
            v0.x = acc[mf][nf][0] + bb0; v0.y = acc[mf][nf][1] + bb1;
            v1.x = acc[mf][nf][2] + bb0; v1.y = acc[mf][nf][3] + bb1;
            *(float2*)(Cm + (size_t)mrow * HH + n0 + ncol) = v0;
            *(float2*)(Cm + (size_t)(mrow + 8) * HH + n0 + ncol) = v1;
        }
    }
}

// ---------------- fused dual-layer persistent recurrence (fp16) -------------
// Superstep s (0..TT):
//   seq0[s]  = relu(xp0[s] + seq0[s-1] @ W0hh^T)                (s <= TT-1)
//   h1[s-1]  = relu(seq0[s-1] @ W1ih^T + b1 + h1[s-2] @ W1hh^T) (s >= 1)
// All weights single fp16 (3 MMAs/ks); activations fp16. Both A-tiles staged
// together -> ONE syncthreads + ONE barrier per superstep. xp0[s] prefetched
// before the sync so its DRAM latency overlaps the MMA loop.
// A/W layout: per-k8-block kb stride 512 B = 4 row-blocks x 128 B, row
// XOR-swizzled by kb&7 (R9-proven addressing, kb*512).
#define FS_W0 0
#define FS_W1 32768
#define FS_WI 65536
#define FS_A1 98304
#define FS_A2 131072
#define FS_TOTAL 163840

__global__ __launch_bounds__(256, 1) void fused_rec(
    const float* __restrict__ xp0,     // [T][B][H]
    const float* __restrict__ W0hh,    // [H][H] fp32
    const float* __restrict__ W1hh,    // [H][H] fp32
    const float* __restrict__ W1ih,    // [H][H] fp32
    const float* __restrict__ b_ih1,
    const float* __restrict__ b_hh1,
    uint32_t* __restrict__ s0ring,     // [2][B][HW] fp16 pairs
    uint32_t* __restrict__ h1ring,     // [2][B][HW] fp16 pairs
    float* __restrict__ h_last)        // [B][H] fp32
{
    extern __shared__ uint8_t sm[];
    uint32_t sb = s2u(sm);

    int cid = blockIdx.x;
    int bt = cid >> 4;                 // 0..7
    int jt = cid & 15;                 // 0..15
    int b0 = bt * 32, j0 = jt * 32;

    int tid = threadIdx.x;
    int lane = tid & 31, wid = tid >> 5;
    int sub = lane >> 3, r8 = lane & 7;
    int mt = wid & 1;                  // 16-row m-tile
    int jb = wid >> 1;                 // 8-col j-block (0..3)

    // ---- preload weight slices (one time): single fp16 --------------------
    for (int idx = tid; idx < 4096; idx += 256) {
        int row = idx >> 7, kq = idx & 127;          // kq: 4-elem group
        int kb = kq >> 1;
        uint32_t off = (uint32_t)kb * 512u + (uint32_t)(row >> 3) * 128u +
                       ((uint32_t)((row & 7) ^ (kb & 7)) << 4) +
                       (uint32_t)(kq & 1) * 8u;
        {
            float4 v = *(const float4*)(W0hh + (size_t)(j0 + row) * HH + kq * 4);
            uint2 w;
            w.x = packh2f4lo(v.x, v.y);
            w.y = packh2f4lo(v.z, v.w);
            *(uint2*)(sm + FS_W0 + off) = w;
        }
        {
            float4 v = *(const float4*)(W1hh + (size_t)(j0 + row) * HH + kq * 4);
            uint2 w;
            w.x = packh2f4lo(v.x, v.y);
            w.y = packh2f4lo(v.z, v.w);
            *(uint2*)(sm + FS_W1 + off) = w;
        }
        {
            float4 v = *(const float4*)(W1ih + (size_t)(j0 + row) * HH + kq * 4);
            uint2 w;
            w.x = packh2f4lo(v.x, v.y);
            w.y = packh2f4lo(v.z, v.w);
            *(uint2*)(sm + FS_WI + off) = w;
        }
    }

    // output fragment coordinates (m16n8 D layout)
    int brow = b0 + mt * 16 + (lane >> 2);
    int jcol = j0 + jb * 8 + (lane & 3) * 2;

    float2 bias1;
    bias1.x = b_ih1[jcol] + b_hh1[jcol];
    bias1.y = b_ih1[jcol + 1] + b_hh1[jcol + 1];

    __syncthreads();   // weights visible CTA-wide

    for (int s = 0; s <= TT; ++s) {
        const int doL0 = (s < TT);
        const int haveA = (s >= 1);
        const int doHH = (s >= 2);

        float acc0[4] = {0.f, 0.f, 0.f, 0.f};
        float accx[4] = {0.f, 0.f, 0.f, 0.f};

        // ---- prefetch xp0[s] (DRAM) — independent of staging/sync --------
        float2 x0 = make_float2(0.f, 0.f), x1 = make_float2(0.f, 0.f);
        if (doL0) {
            const float* xpt = xp0 + (size_t)s * BB * HH;
            x0 = *(const float2*)(xpt + (size_t)brow * HH + jcol);
            x1 = *(const float2*)(xpt + (size_t)(brow + 8) * HH + jcol);
        }

        if (haveA) {
            // ---- stage BOTH A-tiles (straight swizzled uint4 copies) -----
            {
                const uint32_t* hsrc = s0ring + (size_t)((s - 1) & 1) * BB * HW;
#pragma unroll
                for (int it = 0; it < 8; ++it) {
                    int idx = tid + it * 256;
                    int row = idx >> 6, kb = idx & 63;
                    uint4 p = *(const uint4*)(hsrc + (size_t)(b0 + row) * HW +
                                              kb * 4);
                    uint32_t off = (uint32_t)kb * 512u +
                                   (uint32_t)(row >> 3) * 128u +
                                   ((uint32_t)((row & 7) ^ (kb & 7)) << 4);
                    *(uint4*)(sm + FS_A1 + off) = p;
                }
            }
            if (doHH) {
                const uint32_t* hsrc = h1ring + (size_t)(s & 1) * BB * HW;
#pragma unroll
                for (int it = 0; it < 8; ++it) {
                    int idx = tid + it * 256;
                    int row = idx >> 6, kb = idx & 63;
                    uint4 p = *(const uint4*)(hsrc + (size_t)(b0 + row) * HW +
                                              kb * 4);
                    uint32_t off = (uint32_t)kb * 512u +
                                   (uint32_t)(row >> 3) * 128u +
                                   ((uint32_t)((row & 7) ^ (kb & 7)) << 4);
                    *(uint4*)(sm + FS_A2 + off) = p;
                }
            }
            __syncthreads();

            // ---- merged 3-MMA ks loop ------------------------------------
#pragma unroll 4
            for (int ks = 0; ks < 32; ++ks) {
                int kbA = ks * 2 + (sub >> 1);
                uint32_t aoff = (uint32_t)kbA * 512u +
                                (uint32_t)(mt * 2 + (sub & 1)) * 128u +
                                ((uint32_t)(r8 ^ (kbA & 7)) << 4);
                uint32_t a1[4], a2[4];
                ldm_x4(a1[0], a1[1], a1[2], a1[3], sb + FS_A1 + aoff);
                ldm_x4(a2[0], a2[1], a2[2], a2[3], sb + FS_A2 + aoff);

                int kbB = ks * 2 + (sub & 1);
                uint32_t boff = (uint32_t)kbB * 512u + (uint32_t)jb * 128u +
                                ((uint32_t)(r8 ^ (kbB & 7)) << 4);
                uint32_t w00, w01, wi0, wi1, w10, w11;
                ldm_x2(w00, w01, sb + FS_W0 + boff);
                ldm_x2(wi0, wi1, sb + FS_WI + boff);
                ldm_x2(w10, w11, sb + FS_W1 + boff);

                if (doL0) mma_f16(acc0, a1, w00, w01);
                mma_f16(accx, a1, wi0, wi1);
                if (doHH) mma_f16(accx, a2, w10, w11);
            }
        }

        // ---- produce + publish seq0[s] -----------------------------------
        if (doL0) {
            float v0 = fmaxf(acc0[0] + x0.x, 0.f);
            float v1 = fmaxf(acc0[1] + x0.y, 0.f);
            float v2 = fmaxf(acc0[2] + x1.x, 0.f);
            float v3 = fmaxf(acc0[3] + x1.y, 0.f);
            uint32_t* hdst = s0ring + (size_t)(s & 1) * BB * HW;
            hdst[(size_t)brow * HW + (jcol >> 1)] = packh2(v0, v1);
            hdst[(size_t)(brow + 8) * HW + (jcol >> 1)] = packh2(v2, v3);
        }

        // ---- produce + publish h1[s-1] -----------------------------------
        if (haveA) {
            float v0 = fmaxf(accx[0] + bias1.x, 0.f);
            float v1 = fmaxf(accx[1] + bias1.y, 0.f);
            float v2 = fmaxf(accx[2] + bias1.x, 0.f);
            float v3 = fmaxf(accx[3] + bias1.y, 0.f);
            uint32_t* hdst = h1ring + (size_t)((s - 1) & 1) * BB * HW;
            hdst[(size_t)brow * HW + (jcol >> 1)] = packh2(v0, v1);
            hdst[(size_t)(brow + 8) * HW + (jcol >> 1)] = packh2(v2, v3);
            if (s - 1 == TT - 1) {
                *(float2*)(h_last + (size_t)brow * HH + jcol) =
                    make_float2(v0, v1);
                *(float2*)(h_last + (size_t)(brow + 8) * HH + jcol) =
                    make_float2(v2, v3);
            }
        }

        // barrier: publishes rings group-wide; its internal __syncthreads
        // also orders this step's smem MMA reads before next step's staging.
        grp_bar(bt);
    }
}

// ---------------- head: relu(h @ fc1^T + b1) @ fc2^T + b2 -------------------
__global__ __launch_bounds__(256) void head_kernel(
    const float* __restrict__ hl, const float* __restrict__ w1,
    const float* __restrict__ b1f, const float* __restrict__ w2,
    const float* __restrict__ b2f, float* __restrict__ out)
{
    __shared__ float sh[8];
    int b = blockIdx.x;
    int tid = threadIdx.x;
    int w = tid >> 5;
    int lane = tid & 31;

    const float* hb = hl + (size_t)b * HH;
    const float* wr = w1 + (size_t)w * HH;
    float ssum = 0.f;
    for (int k = lane; k < HH; k += 32) ssum += hb[k] * wr[k];
#pragma unroll
    for (int o = 16; o; o >>= 1) ssum += __shfl_xor_sync(0xffffffffu, ssum, o);
    if (lane == 0) sh[w] = fmaxf(ssum + b1f[w], 0.f);
    __syncthreads();
    if (tid < OO) {
        float r = b2f[tid];
#pragma unroll
        for (int j = 0; j < 8; ++j) r += sh[j] * w2[tid * 8 + j];
        out[(size_t)b * OO + tid] = r;
    }
}

// ---------------- launch ----------------------------------------------------
extern "C" void kernel_launch(void* const* d_in, const int* in_sizes, int n_in,
                              void* d_out, int out_size)
{
    const float* x     = (const float*)d_in[0];
    const float* w_ih0 = (const float*)d_in[1];
    const float* w_hh0 = (const float*)d_in[2];
    const float* b_ih0 = (const float*)d_in[3];
    const float* b_hh0 = (const float*)d_in[4];
    const float* w_ih1 = (const float*)d_in[5];
    const float* w_hh1 = (const float*)d_in[6];
    const float* b_ih1 = (const float*)d_in[7];
    const float* b_hh1 = (const float*)d_in[8];
    const float* fc1_w = (const float*)d_in[9];
    const float* fc1_b = (const float*)d_in[10];
    const float* fc2_w = (const float*)d_in[11];
    const float* fc2_b = (const float*)d_in[12];
    float* out = (float*)d_out;

    void* p;
    cudaGetSymbolAddress(&p, g_xp0);   float* xp0 = (float*)p;
    cudaGetSymbolAddress(&p, g_s0);    uint32_t* s0ring = (uint32_t*)p;
    cudaGetSymbolAddress(&p, g_h1);    uint32_t* h1ring = (uint32_t*)p;
    cudaGetSymbolAddress(&p, g_hlast); float* hlast = (float*)p;
    cudaGetSymbolAddress(&p, g_w0h);   __nv_bfloat16* w0h = (__nv_bfloat16*)p;
    cudaGetSymbolAddress(&p, g_w0l);   __nv_bfloat16* w0l = (__nv_bfloat16*)p;

    cudaFuncSetAttribute(fused_rec,
                         cudaFuncAttributeMaxDynamicSharedMemorySize,
                         FS_TOTAL);

    dim3 gg(TT * BB / 128, HH / 128);   // 512 x 4

    // layer-0 input projection weights -> bf16 hi/lo
    convert_w0<<<(HH * DD + 255) / 256, 256>>>(w_ih0);
    // layer-0 input projection: xp0 = x @ w_ih0^T + b_ih0 + b_hh0
    gemm_hmma<<<gg, 256>>>(x, w0h, w0l, b_ih0, b_hh0, xp0, DD, 1);
    // fused dual-layer recurrence (fp16 weights+activations, 3-MMA loop)
    fused_rec<<<NBLK, 256, FS_TOTAL>>>(xp0, w_hh0, w_hh1, w_ih1,
                                       b_ih1, b_hh1, s0ring, h1ring, hlast);
    // head
    head_kernel<<<BB, 256>>>(hlast, fc1_w, fc1_b, fc2_w, fc2_b, out);
}

// round 15
// speedup vs baseline: 3.0945x; 1.0589x over previous
#include <cuda_runtime.h>
#include <cuda_bf16.h>
#include <cuda_fp16.h>
#include <cstdint>

#define BB 256     // batch
#define TT 256     // time steps
#define DD 64      // input dim
#define HH 512     // hidden
#define OO 10      // output classes

#define NBLK 128   // fused rec grid: 8 bt x 16 jt (all co-resident, 1/SM)
#define GRP  16    // CTAs per bt dependency group
#define HW   (HH / 2)   // packed fp16-pair row stride (uint32 units)

// ---------------- scratch (static device globals; no allocation allowed) ----
__device__ uint32_t g_xp0[TT * BB * HW];     // [t][b][h/2] fp16 pairs
__device__ uint32_t g_s0[2][BB * HW];        // seq0 ring, fp16 pairs
__device__ uint32_t g_h1[2][BB * HW];        // layer-1 h ring, fp16 pairs
__device__ float    g_hlast[BB * HH];

__device__ unsigned g_gcnt[8];               // per-bt arrival counters
__device__ unsigned g_ggen[8];               // per-bt generation (monotonic)

// bf16 split weights for the layer-0 input projection GEMM
__device__ __nv_bfloat16 g_w0h[HH * DD], g_w0l[HH * DD];

// ---------------- per-group sense barrier (16 CTAs sharing bt) --------------
__device__ __forceinline__ void grp_bar(int bt) {
    __syncthreads();
    if (threadIdx.x == 0) {
        __threadfence();   // release
        unsigned snap = *(volatile unsigned*)&g_ggen[bt];
        unsigned old = atomicAdd(&g_gcnt[bt], 1u);
        if (old == GRP - 1u) {
            g_gcnt[bt] = 0u;
            __threadfence();
            atomicExch(&g_ggen[bt], snap + 1u);
        } else {
            while (*(volatile unsigned*)&g_ggen[bt] == snap) {}
            __threadfence();  // acquire
        }
    }
    __syncthreads();
}

// ---------------- MMA plumbing ----------------------------------------------
__device__ __forceinline__ uint32_t s2u(const void* p) {
    uint32_t a;
    asm("{ .reg .u64 t; cvta.to.shared.u64 t, %1; cvt.u32.u64 %0, t; }"
        : "=r"(a) : "l"(p));
    return a;
}
__device__ __forceinline__ void ldm_x4(uint32_t& r0, uint32_t& r1,
                                       uint32_t& r2, uint32_t& r3,
                                       uint32_t addr) {
    asm volatile("ldmatrix.sync.aligned.m8n8.x4.shared.b16 {%0,%1,%2,%3}, [%4];"
                 : "=r"(r0), "=r"(r1), "=r"(r2), "=r"(r3) : "r"(addr));
}
__device__ __forceinline__ void ldm_x2(uint32_t& r0, uint32_t& r1,
                                       uint32_t addr) {
    asm volatile("ldmatrix.sync.aligned.m8n8.x2.shared.b16 {%0,%1}, [%2];"
                 : "=r"(r0), "=r"(r1) : "r"(addr));
}
__device__ __forceinline__ void mma_bf16(float* d, const uint32_t* a,
                                         uint32_t b0, uint32_t b1) {
    asm volatile(
        "mma.sync.aligned.m16n8k16.row.col.f32.bf16.bf16.f32 "
        "{%0,%1,%2,%3}, {%4,%5,%6,%7}, {%8,%9}, {%0,%1,%2,%3};"
        : "+f"(d[0]), "+f"(d[1]), "+f"(d[2]), "+f"(d[3])
        : "r"(a[0]), "r"(a[1]), "r"(a[2]), "r"(a[3]), "r"(b0), "r"(b1));
}
__device__ __forceinline__ void mma_f16(float* d, const uint32_t* a,
                                        uint32_t b0, uint32_t b1) {
    asm volatile(
        "mma.sync.aligned.m16n8k16.row.col.f32.f16.f16.f32 "
        "{%0,%1,%2,%3}, {%4,%5,%6,%7}, {%8,%9}, {%0,%1,%2,%3};"
        : "+f"(d[0]), "+f"(d[1]), "+f"(d[2]), "+f"(d[3])
        : "r"(a[0]), "r"(a[1]), "r"(a[2]), "r"(a[3]), "r"(b0), "r"(b1));
}
__device__ __forceinline__ uint32_t packsplit(float v) {
    __nv_bfloat16 h = __float2bfloat16(v);
    __nv_bfloat16 l = __float2bfloat16(v - __bfloat162float(h));
    return (uint32_t)__bfloat16_as_ushort(h) |
           ((uint32_t)__bfloat16_as_ushort(l) << 16);
}
__device__ __forceinline__ uint32_t packh2(float lo, float hi) {
    __half2 h = __floats2half2_rn(lo, hi);   // .x = lo (low 16 bits)
    uint32_t u;
    asm("mov.b32 %0, %1;" : "=r"(u) : "r"(*(uint32_t*)&h));
    return u;
}
__device__ __forceinline__ uint32_t packh2f4lo(float x, float y) {
    return (uint32_t)__half_as_ushort(__float2half_rn(x)) |
           ((uint32_t)__half_as_ushort(__float2half_rn(y)) << 16);
}
__device__ __forceinline__ float2 unpackh2(uint32_t u) {
    __half2 h = *(__half2*)&u;
    return __half22float2(h);
}

// ---------------- weight convert: fp32 -> bf16 hi/lo (layer-0 inproj) -------
__global__ void convert_w0(const float* __restrict__ w0) {
    int i = blockIdx.x * 256 + threadIdx.x;
    if (i < HH * DD) {
        float v = w0[i];
        __nv_bfloat16 h = __float2bfloat16(v);
        g_w0h[i] = h;
        g_w0l[i] = __float2bfloat16(v - __bfloat162float(h));
    }
}

// ---------------- HMMA GEMM: Cm(packed fp16) = A @ W^T + b1 + b2 ------------
// Split bf16: C = Ah*Wh + Ah*Wl + Al*Wh, fp32 accum. Output packed __half2.
#define HM_AH 0
#define HM_AL 8192
#define HM_WH 16384
#define HM_WL 24576
#define HM_SB 32768
#define HM_TOTAL (32768 + 512)

__global__ __launch_bounds__(256, 2) void gemm_hmma(
    const float* __restrict__ A,
    const __nv_bfloat16* __restrict__ Wh, const __nv_bfloat16* __restrict__ Wl,
    const float* __restrict__ b1, const float* __restrict__ b2,
    uint32_t* __restrict__ Cm, int K, int permute)
{
    __shared__ __align__(128) uint8_t sm[HM_TOTAL];
    uint32_t sbase = s2u(sm);

    int tid = threadIdx.x;
    int lane = tid & 31;
    int wid = tid >> 5;
    int wm = wid & 3;
    int wn = wid >> 2;
    int m0 = blockIdx.x * 128;
    int n0 = blockIdx.y * 128;

    if (tid < 128) {
        int n = n0 + tid;
        ((float*)(sm + HM_SB))[tid] = b1[n] + (b2 ? b2[n] : 0.f);
    }

    const float* Ap[4];
#pragma unroll
    for (int it = 0; it < 4; ++it) {
        int idx = tid + it * 256;
        int row = idx >> 3;
        int gm = m0 + row;
        if (permute) {
            int b_ = gm & (BB - 1);
            int t_ = gm >> 8;                  // BB == 256
            Ap[it] = A + ((size_t)b_ * TT + t_) * K;
        } else {
            Ap[it] = A + (size_t)gm * K;
        }
    }

    float acc[2][8][4];
#pragma unroll
    for (int mf = 0; mf < 2; ++mf)
#pragma unroll
        for (int nf = 0; nf < 8; ++nf)
#pragma unroll
            for (int q = 0; q < 4; ++q) acc[mf][nf][q] = 0.f;

    int sub = lane >> 3;
    int r8  = lane & 7;

    int nch = K >> 5;
    for (int c = 0; c < nch; ++c) {
        int kc = c << 5;
        __syncthreads();

#pragma unroll
        for (int it = 0; it < 4; ++it) {
            int idx = tid + it * 256;
            int row = idx >> 3, kq = idx & 7;
            float4 v = *(const float4*)(Ap[it] + kc + kq * 4);
            uint32_t s0 = packsplit(v.x), s1 = packsplit(v.y);
            uint32_t s2 = packsplit(v.z), s3 = packsplit(v.w);
            uint2 hp, lp;
            hp.x = (s0 & 0xffffu) | (s1 << 16);
            hp.y = (s2 & 0xffffu) | (s3 << 16);
            lp.x = (s0 >> 16) | (s1 & 0xffff0000u);
            lp.y = (s2 >> 16) | (s3 & 0xffff0000u);
            int kt = kq >> 1, kcol = (kq & 1) * 4;
            uint32_t off = (uint32_t)(((kt * 16) + (row >> 3)) * 128 +
                                      (row & 7) * 16 + kcol * 2);
            *(uint2*)(sm + HM_AH + off) = hp;
            *(uint2*)(sm + HM_AL + off) = lp;
        }
#pragma unroll
        for (int it = 0; it < 4; ++it) {
            int idx = tid + it * 256;
            int row = idx >> 3, kq = idx & 7;
            size_t go = (size_t)(n0 + row) * K + kc + kq * 4;
            uint2 hv = *(const uint2*)(Wh + go);
            uint2 lv = *(const uint2*)(Wl + go);
            int kt = kq >> 1, kcol = (kq & 1) * 4;
            uint32_t off = (uint32_t)(((kt * 16) + (row >> 3)) * 128 +
                                      (row & 7) * 16 + kcol * 2);
            *(uint2*)(sm + HM_WH + off) = hv;
            *(uint2*)(sm + HM_WL + off) = lv;
        }
        __syncthreads();

#pragma unroll
        for (int s = 0; s < 2; ++s) {
            uint32_t ah[2][4], al[2][4];
#pragma unroll
            for (int mf = 0; mf < 2; ++mf) {
                int mt = wm * 4 + mf * 2 + (sub & 1);
                int kt = s * 2 + (sub >> 1);
                uint32_t ad = sbase + HM_AH +
                              (uint32_t)(((kt * 16) + mt) * 128 + r8 * 16);
                ldm_x4(ah[mf][0], ah[mf][1], ah[mf][2], ah[mf][3], ad);
                ldm_x4(al[mf][0], al[mf][1], al[mf][2], al[mf][3],
                       ad + (HM_AL - HM_AH));
            }
#pragma unroll
            for (int nf = 0; nf < 8; ++nf) {
                int nt = wn * 8 + nf;
                int ktb = s * 2 + (sub & 1);
                uint32_t bd = sbase + HM_WH +
                              (uint32_t)(((ktb * 16) + nt) * 128 + r8 * 16);
                uint32_t bh0, bh1, bl0, bl1;
                ldm_x2(bh0, bh1, bd);
                ldm_x2(bl0, bl1, bd + (HM_WL - HM_WH));
                mma_bf16(acc[0][nf], ah[0], bh0, bh1);
                mma_bf16(acc[1][nf], ah[1], bh0, bh1);
                mma_bf16(acc[0][nf], ah[0], bl0, bl1);
                mma_bf16(acc[1][nf], ah[1], bl0, bl1);
                mma_bf16(acc[0][nf], al[0], bh0, bh1);
                mma_bf16(acc[1][nf], al[1], bh0, bh1);
            }
        }
    }

    const float* sb = (const float*)(sm + HM_SB);
#pragma unroll
    for (int mf = 0; mf < 2; ++mf) {
        int mrow = m0 + wm * 32 + mf * 16 + (lane >> 2);
#pragma unroll
        for (int nf = 0; nf < 8; ++nf) {
            int ncol = wn * 64 + nf * 8 + (lane & 3) * 2;
            float bb0 = sb[ncol], bb1 = sb[ncol + 1];
            int gc = (n0 + ncol) >> 1;
            Cm[(size_t)mrow * HW + gc] =
                packh2(acc[mf][nf][0] + bb0, acc[mf][nf][1] + bb1);
            Cm[(size_t)(mrow + 8) * HW + gc] =
                packh2(acc[mf][nf][2] + bb0, acc[mf][nf][3] + bb1);
        }
    }
}

// ---------------- fused dual-layer persistent recurrence (fp16) -------------
// Superstep s (0..TT):
//   seq0[s]  = relu(xp0[s] + seq0[s-1] @ W0hh^T)                (s <= TT-1)
//   h1[s-1]  = relu(seq0[s-1] @ W1ih^T + b1 + h1[s-2] @ W1hh^T) (s >= 1)
// Split-staged pipeline: stage A1, LDG A2 into regs, sync, phase-1 MMAs
// (W0hh+W1ih on A1) hide A2's L2 latency, STS A2, sync, phase-2 MMAs (W1hh).
// xp0 packed fp16. A/W layout: kb*512 stride, XOR swizzle by kb&7 (R9-proven).
#define FS_W0 0
#define FS_W1 32768
#define FS_WI 65536
#define FS_A1 98304
#define FS_A2 131072
#define FS_TOTAL 163840

__global__ __launch_bounds__(256, 1) void fused_rec(
    const uint32_t* __restrict__ xp0,  // [T][B][HW] fp16 pairs
    const float* __restrict__ W0hh,    // [H][H] fp32
    const float* __restrict__ W1hh,    // [H][H] fp32
    const float* __restrict__ W1ih,    // [H][H] fp32
    const float* __restrict__ b_ih1,
    const float* __restrict__ b_hh1,
    uint32_t* __restrict__ s0ring,     // [2][B][HW] fp16 pairs
    uint32_t* __restrict__ h1ring,     // [2][B][HW] fp16 pairs
    float* __restrict__ h_last)        // [B][H] fp32
{
    extern __shared__ uint8_t sm[];
    uint32_t sb = s2u(sm);

    int cid = blockIdx.x;
    int bt = cid >> 4;                 // 0..7
    int jt = cid & 15;                 // 0..15
    int b0 = bt * 32, j0 = jt * 32;

    int tid = threadIdx.x;
    int lane = tid & 31, wid = tid >> 5;
    int sub = lane >> 3, r8 = lane & 7;
    int mt = wid & 1;                  // 16-row m-tile
    int jb = wid >> 1;                 // 8-col j-block (0..3)

    // ---- preload weight slices (one time): single fp16 --------------------
    for (int idx = tid; idx < 4096; idx += 256) {
        int row = idx >> 7, kq = idx & 127;
        int kb = kq >> 1;
        uint32_t off = (uint32_t)kb * 512u + (uint32_t)(row >> 3) * 128u +
                       ((uint32_t)((row & 7) ^ (kb & 7)) << 4) +
                       (uint32_t)(kq & 1) * 8u;
        {
            float4 v = *(const float4*)(W0hh + (size_t)(j0 + row) * HH + kq * 4);
            uint2 w;
            w.x = packh2f4lo(v.x, v.y);
            w.y = packh2f4lo(v.z, v.w);
            *(uint2*)(sm + FS_W0 + off) = w;
        }
        {
            float4 v = *(const float4*)(W1hh + (size_t)(j0 + row) * HH + kq * 4);
            uint2 w;
            w.x = packh2f4lo(v.x, v.y);
            w.y = packh2f4lo(v.z, v.w);
            *(uint2*)(sm + FS_W1 + off) = w;
        }
        {
            float4 v = *(const float4*)(W1ih + (size_t)(j0 + row) * HH + kq * 4);
            uint2 w;
            w.x = packh2f4lo(v.x, v.y);
            w.y = packh2f4lo(v.z, v.w);
            *(uint2*)(sm + FS_WI + off) = w;
        }
    }

    // output fragment coordinates (m16n8 D layout)
    int brow = b0 + mt * 16 + (lane >> 2);
    int jcol = j0 + jb * 8 + (lane & 3) * 2;

    float2 bias1;
    bias1.x = b_ih1[jcol] + b_hh1[jcol];
    bias1.y = b_ih1[jcol + 1] + b_hh1[jcol + 1];

    __syncthreads();   // weights visible CTA-wide

    for (int s = 0; s <= TT; ++s) {
        const int doL0 = (s < TT);
        const int haveA = (s >= 1);
        const int doHH = (s >= 2);

        float acc0[4] = {0.f, 0.f, 0.f, 0.f};
        float accx[4] = {0.f, 0.f, 0.f, 0.f};

        // ---- prefetch xp0[s] (packed) — independent of staging/sync ------
        uint32_t xa = 0u, xb = 0u;
        if (doL0) {
            const uint32_t* xpt = xp0 + (size_t)s * BB * HW;
            xa = xpt[(size_t)brow * HW + (jcol >> 1)];
            xb = xpt[(size_t)(brow + 8) * HW + (jcol >> 1)];
        }

        if (haveA) {
            // ---- stage A1 (seq0[s-1]) to smem --------------------------
            {
                const uint32_t* hsrc = s0ring + (size_t)((s - 1) & 1) * BB * HW;
#pragma unroll
                for (int it = 0; it < 8; ++it) {
                    int idx = tid + it * 256;
                    int row = idx >> 6, kb = idx & 63;
                    uint4 p = *(const uint4*)(hsrc + (size_t)(b0 + row) * HW +
                                              kb * 4);
                    uint32_t off = (uint32_t)kb * 512u +
                                   (uint32_t)(row >> 3) * 128u +
                                   ((uint32_t)((row & 7) ^ (kb & 7)) << 4);
                    *(uint4*)(sm + FS_A1 + off) = p;
                }
            }
            // ---- LDG A2 (h1[s-2]) into regs (latency hidden by phase 1) --
            uint4 a2r[8];
            if (doHH) {
                const uint32_t* hsrc = h1ring + (size_t)(s & 1) * BB * HW;
#pragma unroll
                for (int it = 0; it < 8; ++it) {
                    int idx = tid + it * 256;
                    int row = idx >> 6, kb = idx & 63;
                    a2r[it] = *(const uint4*)(hsrc + (size_t)(b0 + row) * HW +
                                              kb * 4);
                }
            }
            __syncthreads();   // A1 visible

            // ---- phase 1: acc0 += A1@W0hh, accx += A1@W1ih ---------------
#pragma unroll 4
            for (int ks = 0; ks < 32; ++ks) {
                int kbA = ks * 2 + (sub >> 1);
                uint32_t aoff = (uint32_t)kbA * 512u +
                                (uint32_t)(mt * 2 + (sub & 1)) * 128u +
                                ((uint32_t)(r8 ^ (kbA & 7)) << 4);
                uint32_t a1[4];
                ldm_x4(a1[0], a1[1], a1[2], a1[3], sb + FS_A1 + aoff);

                int kbB = ks * 2 + (sub & 1);
                uint32_t boff = (uint32_t)kbB * 512u + (uint32_t)jb * 128u +
                                ((uint32_t)(r8 ^ (kbB & 7)) << 4);
                uint32_t w00, w01, wi0, wi1;
                ldm_x2(w00, w01, sb + FS_W0 + boff);
                ldm_x2(wi0, wi1, sb + FS_WI + boff);

                if (doL0) mma_f16(acc0, a1, w00, w01);
                mma_f16(accx, a1, wi0, wi1);
            }

            // ---- STS A2 + phase 2: accx += A2@W1hh -----------------------
            if (doHH) {
#pragma unroll
                for (int it = 0; it < 8; ++it) {
                    int idx = tid + it * 256;
                    int row = idx >> 6, kb = idx & 63;
                    uint32_t off = (uint32_t)kb * 512u +
                                   (uint32_t)(row >> 3) * 128u +
                                   ((uint32_t)((row & 7) ^ (kb & 7)) << 4);
                    *(uint4*)(sm + FS_A2 + off) = a2r[it];
                }
            }
            __syncthreads();   // A2 visible (and A1 reads complete)

            if (doHH) {
#pragma unroll 4
                for (int ks = 0; ks < 32; ++ks) {
                    int kbA = ks * 2 + (sub >> 1);
                    uint32_t aoff = (uint32_t)kbA * 512u +
                                    (uint32_t)(mt * 2 + (sub & 1)) * 128u +
                                    ((uint32_t)(r8 ^ (kbA & 7)) << 4);
                    uint32_t a2[4];
                    ldm_x4(a2[0], a2[1], a2[2], a2[3], sb + FS_A2 + aoff);

                    int kbB = ks * 2 + (sub & 1);
                    uint32_t boff = (uint32_t)kbB * 512u +
                                    (uint32_t)jb * 128u +
                                    ((uint32_t)(r8 ^ (kbB & 7)) << 4);
                    uint32_t w10, w11;
                    ldm_x2(w10, w11, sb + FS_W1 + boff);
                    mma_f16(accx, a2, w10, w11);
                }
            }
        }

        // ---- produce + publish seq0[s] -----------------------------------
        if (doL0) {
            float2 x0 = unpackh2(xa);
            float2 x1 = unpackh2(xb);
            float v0 = fmaxf(acc0[0] + x0.x, 0.f);
            float v1 = fmaxf(acc0[1] + x0.y, 0.f);
            float v2 = fmaxf(acc0[2] + x1.x, 0.f);
            float v3 = fmaxf(acc0[3] + x1.y, 0.f);
            uint32_t* hdst = s0ring + (size_t)(s & 1) * BB * HW;
            hdst[(size_t)brow * HW + (jcol >> 1)] = packh2(v0, v1);
            hdst[(size_t)(brow + 8) * HW + (jcol >> 1)] = packh2(v2, v3);
        }

        // ---- produce + publish h1[s-1] -----------------------------------
        if (haveA) {
            float v0 = fmaxf(accx[0] + bias1.x, 0.f);
            float v1 = fmaxf(accx[1] + bias1.y, 0.f);
            float v2 = fmaxf(accx[2] + bias1.x, 0.f);
            float v3 = fmaxf(accx[3] + bias1.y, 0.f);
            uint32_t* hdst = h1ring + (size_t)((s - 1) & 1) * BB * HW;
            hdst[(size_t)brow * HW + (jcol >> 1)] = packh2(v0, v1);
            hdst[(size_t)(brow + 8) * HW + (jcol >> 1)] = packh2(v2, v3);
            if (s - 1 == TT - 1) {
                *(float2*)(h_last + (size_t)brow * HH + jcol) =
                    make_float2(v0, v1);
                *(float2*)(h_last + (size_t)(brow + 8) * HH + jcol) =
                    make_float2(v2, v3);
            }
        }

        // barrier: publishes rings group-wide; its internal __syncthreads
        // also orders this step's smem MMA reads before next step's staging.
        grp_bar(bt);
    }
}

// ---------------- head: relu(h @ fc1^T + b1) @ fc2^T + b2 -------------------
__global__ __launch_bounds__(256) void head_kernel(
    const float* __restrict__ hl, const float* __restrict__ w1,
    const float* __restrict__ b1f, const float* __restrict__ w2,
    const float* __restrict__ b2f, float* __restrict__ out)
{
    __shared__ float sh[8];
    int b = blockIdx.x;
    int tid = threadIdx.x;
    int w = tid >> 5;
    int lane = tid & 31;

    const float* hb = hl + (size_t)b * HH;
    const float* wr = w1 + (size_t)w * HH;
    float ssum = 0.f;
    for (int k = lane; k < HH; k += 32) ssum += hb[k] * wr[k];
#pragma unroll
    for (int o = 16; o; o >>= 1) ssum += __shfl_xor_sync(0xffffffffu, ssum, o);
    if (lane == 0) sh[w] = fmaxf(ssum + b1f[w], 0.f);
    __syncthreads();
    if (tid < OO) {
        float r = b2f[tid];
#pragma unroll
        for (int j = 0; j < 8; ++j) r += sh[j] * w2[tid * 8 + j];
        out[(size_t)b * OO + tid] = r;
    }
}

// ---------------- launch ----------------------------------------------------
extern "C" void kernel_launch(void* const* d_in, const int* in_sizes, int n_in,
                              void* d_out, int out_size)
{
    const float* x     = (const float*)d_in[0];
    const float* w_ih0 = (const float*)d_in[1];
    const float* w_hh0 = (const float*)d_in[2];
    const float* b_ih0 = (const float*)d_in[3];
    const float* b_hh0 = (const float*)d_in[4];
    const float* w_ih1 = (const float*)d_in[5];
    const float* w_hh1 = (const float*)d_in[6];
    const float* b_ih1 = (const float*)d_in[7];
    const float* b_hh1 = (const float*)d_in[8];
    const float* fc1_w = (const float*)d_in[9];
    const float* fc1_b = (const float*)d_in[10];
    const float* fc2_w = (const float*)d_in[11];
    const float* fc2_b = (const float*)d_in[12];
    float* out = (float*)d_out;

    void* p;
    cudaGetSymbolAddress(&p, g_xp0);   uint32_t* xp0 = (uint32_t*)p;
    cudaGetSymbolAddress(&p, g_s0);    uint32_t* s0ring = (uint32_t*)p;
    cudaGetSymbolAddress(&p, g_h1);    uint32_t* h1ring = (uint32_t*)p;
    cudaGetSymbolAddress(&p, g_hlast); float* hlast = (float*)p;
    cudaGetSymbolAddress(&p, g_w0h);   __nv_bfloat16* w0h = (__nv_bfloat16*)p;
    cudaGetSymbolAddress(&p, g_w0l);   __nv_bfloat16* w0l = (__nv_bfloat16*)p;

    cudaFuncSetAttribute(fused_rec,
                         cudaFuncAttributeMaxDynamicSharedMemorySize,
                         FS_TOTAL);

    dim3 gg(TT * BB / 128, HH / 128);   // 512 x 4

    // layer-0 input projection weights -> bf16 hi/lo
    convert_w0<<<(HH * DD + 255) / 256, 256>>>(w_ih0);
    // layer-0 input projection: xp0 = x @ w_ih0^T + b_ih0 + b_hh0 (fp16 out)
    gemm_hmma<<<gg, 256>>>(x, w0h, w0l, b_ih0, b_hh0, xp0, DD, 1);
    // fused dual-layer recurrence (split-staged pipeline)
    fused_rec<<<NBLK, 256, FS_TOTAL>>>(xp0, w_hh0, w_hh1, w_ih1,
                                       b_ih1, b_hh1, s0ring, h1ring, hlast);
    // head
    head_kernel<<<BB, 256>>>(hlast, fc1_w, fc1_b, fc2_w, fc2_b, out);
}